// round 8
// baseline (speedup 1.0000x reference)
#include <cuda_runtime.h>
#include <cuda_bf16.h>
#include <math.h>
#include <stdint.h>

#define NB 64
#define TT 512
#define DD 1024
#define HH 1024
#define FOURH 4096
#define P_CTAS 128

// ---------------------------------------------------------------------------
// Scratch (__device__ globals; allocation-free rule)
// ---------------------------------------------------------------------------
__device__ float          g_xw[(size_t)NB * TT * FOURH];      // 512 MiB xW+b (permuted cols)
__device__ __nv_bfloat16  g_xhi[(size_t)NB * TT * DD];        // 64 MiB
__device__ __nv_bfloat16  g_xlo[(size_t)NB * TT * DD];        // 64 MiB
__device__ __nv_bfloat16  g_wxt_hi[(size_t)FOURH * DD];       // WxT perm [j'][k]
__device__ __nv_bfloat16  g_wxt_lo[(size_t)FOURH * DD];
__device__ __nv_bfloat16  g_wht_hi[(size_t)FOURH * DD];       // WhT perm [j'][k]
__device__ __nv_bfloat16  g_wht_lo[(size_t)FOURH * DD];
__device__ __nv_bfloat16  g_h_hi[2][NB * HH];                 // h double buffer (bf16 hi)
__device__ __nv_bfloat16  g_h_lo[2][NB * HH];                 // h double buffer (bf16 lo)
__device__ float          g_biasp[FOURH];                     // permuted bias
__device__ unsigned       g_gflag[16];                        // per producer-group counters

// ---------------------------------------------------------------------------
// Helpers
// ---------------------------------------------------------------------------
__device__ __forceinline__ uint32_t smem_u32(const void* p) {
    uint32_t a;
    asm("{ .reg .u64 t; cvta.to.shared.u64 t, %1; cvt.u32.u64 %0, t; }"
        : "=r"(a) : "l"(p));
    return a;
}
__device__ __forceinline__ unsigned ld_acq(const unsigned* p) {
    unsigned v;
    asm volatile("ld.global.acquire.gpu.u32 %0, [%1];" : "=r"(v) : "l"(p) : "memory");
    return v;
}

#define CP16(dst, src) \
    asm volatile("cp.async.cg.shared.global [%0], [%1], 16;" :: "r"(dst), "l"(src) : "memory")
#define CP_COMMIT() asm volatile("cp.async.commit_group;" ::: "memory")
#define CP_WAIT(n)  asm volatile("cp.async.wait_group %0;" :: "n"(n) : "memory")

#define LDSM4(r0, r1, r2, r3, addr) \
    asm volatile("ldmatrix.sync.aligned.m8n8.x4.shared.b16 {%0,%1,%2,%3}, [%4];" \
                 : "=r"(r0), "=r"(r1), "=r"(r2), "=r"(r3) : "r"(addr))

#define MMA_BF16(c0, c1, c2, c3, a0, a1, a2, a3, b0, b1) \
    asm volatile("mma.sync.aligned.m16n8k16.row.col.f32.bf16.bf16.f32 " \
                 "{%0,%1,%2,%3}, {%4,%5,%6,%7}, {%8,%9}, {%0,%1,%2,%3};" \
                 : "+f"(c0), "+f"(c1), "+f"(c2), "+f"(c3) \
                 : "r"(a0), "r"(a1), "r"(a2), "r"(a3), "r"(b0), "r"(b1))

__device__ __forceinline__ float fsigmoid(float x) { return 1.0f / (1.0f + __expf(-x)); }
__device__ __forceinline__ float ftanh(float x)    { return 2.0f / (1.0f + __expf(-2.0f * x)) - 1.0f; }

// ---------------------------------------------------------------------------
// Prep kernels
// ---------------------------------------------------------------------------
__global__ void prep_small_kernel(const float* __restrict__ h0, const float* __restrict__ b) {
    int i = blockIdx.x * 1024 + threadIdx.x;
    if (i < 16) g_gflag[i] = 0u;
    if (i < NB * HH) {
        float v = h0[i];
        __nv_bfloat16 hi = __float2bfloat16(v);
        g_h_hi[0][i] = hi;
        g_h_lo[0][i] = __float2bfloat16(v - __bfloat162float(hi));
    }
    if (i < FOURH) {
        int jp = (i & 1023) * 4 + (i >> 10);     // perm: col g*1024+jh -> jh*4+g
        g_biasp[jp] = b[i];
    }
}

__global__ void split_x_kernel(const float* __restrict__ x) {
    size_t i = ((size_t)blockIdx.x * 256 + threadIdx.x) * 4;
    float4 v = *(const float4*)(x + i);
    __nv_bfloat16 h0 = __float2bfloat16(v.x), h1 = __float2bfloat16(v.y);
    __nv_bfloat16 h2 = __float2bfloat16(v.z), h3 = __float2bfloat16(v.w);
    __nv_bfloat162* ph = (__nv_bfloat162*)(g_xhi + i);
    __nv_bfloat162* pl = (__nv_bfloat162*)(g_xlo + i);
    ph[0] = __nv_bfloat162(h0, h1);
    ph[1] = __nv_bfloat162(h2, h3);
    pl[0] = __nv_bfloat162(__float2bfloat16(v.x - __bfloat162float(h0)),
                           __float2bfloat16(v.y - __bfloat162float(h1)));
    pl[1] = __nv_bfloat162(__float2bfloat16(v.z - __bfloat162float(h2)),
                           __float2bfloat16(v.w - __bfloat162float(h3)));
}

// W (1024 x 4096, k-major rows) -> out[j'][k] bf16 hi/lo with gate permutation.
__global__ void transpose_split_kernel(const float* __restrict__ W,
                                       __nv_bfloat16* __restrict__ ohi,
                                       __nv_bfloat16* __restrict__ olo) {
    __shared__ float ts[32][33];
    const int k0 = blockIdx.x * 32;
    const int c0 = blockIdx.y * 32;
    const int tx = threadIdx.x, ty = threadIdx.y;  // 32 x 8
    #pragma unroll
    for (int i = 0; i < 4; i++)
        ts[ty + 8 * i][tx] = W[(size_t)(k0 + ty + 8 * i) * FOURH + c0 + tx];
    __syncthreads();
    #pragma unroll
    for (int i = 0; i < 4; i++) {
        int c = c0 + ty + 8 * i;
        int jp = (c & 1023) * 4 + (c >> 10);
        float v = ts[tx][ty + 8 * i];
        __nv_bfloat16 hi = __float2bfloat16(v);
        ohi[(size_t)jp * DD + k0 + tx] = hi;
        olo[(size_t)jp * DD + k0 + tx] = __float2bfloat16(v - __bfloat162float(hi));
    }
}

// ---------------------------------------------------------------------------
// xW GEMM via mma.sync (unchanged working version)
// ---------------------------------------------------------------------------
#define G_STAGE 65536   // Ah 16K | Al 16K | Bh 16K | Bl 16K
#define G_SMEM  (3 * G_STAGE)

__global__ __launch_bounds__(256, 1)
void xw_gemm_mma() {
    extern __shared__ char smem[];
    const uint32_t sb = smem_u32(smem);
    const int tid = threadIdx.x;
    const int nbase = blockIdx.x * 128;
    const int mbase = blockIdx.y * 128;

    const __nv_bfloat16* Ahg = g_xhi + (size_t)mbase * DD;
    const __nv_bfloat16* Alg = g_xlo + (size_t)mbase * DD;
    const __nv_bfloat16* Bhg = g_wxt_hi + (size_t)nbase * DD;
    const __nv_bfloat16* Blg = g_wxt_lo + (size_t)nbase * DD;

    auto cp_chunk = [&](int c, int st) {
        const int k0 = c * 64;
        const uint32_t ah = sb + st * G_STAGE;
        #pragma unroll
        for (int i = 0; i < 4; i++) {
            int idx = tid + i * 256;
            int row = idx >> 3, ch = idx & 7;
            uint32_t o = (uint32_t)(row * 128) + (uint32_t)((ch * 16) ^ ((row & 7) * 16));
            CP16(ah + o,         (const char*)(Ahg + (size_t)row * DD + k0) + ch * 16);
            CP16(ah + 16384 + o, (const char*)(Alg + (size_t)row * DD + k0) + ch * 16);
            CP16(ah + 32768 + o, (const char*)(Bhg + (size_t)row * DD + k0) + ch * 16);
            CP16(ah + 49152 + o, (const char*)(Blg + (size_t)row * DD + k0) + ch * 16);
        }
        CP_COMMIT();
    };

    const int wid = tid >> 5, lane = tid & 31;
    const int wm = wid >> 2, wn = wid & 3;      // warp grid 2x4
    const int m0 = wm * 64, n0 = wn * 32;
    const int gid = lane >> 2, tig = lane & 3;

    const int a_r = lane & 15;
    const uint32_t a_k = ((lane >> 4) & 1) * 16;
    const uint32_t a_x = (uint32_t)((a_r & 7) * 16);
    const int b_r = (lane & 7) + ((lane >> 4) & 1) * 8;
    const uint32_t b_k = ((lane >> 3) & 1) * 16;
    const uint32_t b_x = (uint32_t)((lane & 7) * 16);

    float acc[4][4][4];
    #pragma unroll
    for (int mt = 0; mt < 4; mt++)
        #pragma unroll
        for (int nt = 0; nt < 4; nt++)
            #pragma unroll
            for (int q = 0; q < 4; q++) acc[mt][nt][q] = 0.0f;

    cp_chunk(0, 0);
    cp_chunk(1, 1);

    for (int c = 0; c < 16; c++) {
        if (c + 2 < 16) { cp_chunk(c + 2, (c + 2) % 3); CP_WAIT(2); }
        else if (c + 1 < 16) { CP_WAIT(1); }
        else { CP_WAIT(0); }
        __syncthreads();

        const uint32_t base = sb + (c % 3) * G_STAGE;
        #pragma unroll
        for (int kk = 0; kk < 4; kk++) {
            const uint32_t ka = ((uint32_t)(kk * 32) + a_k) ^ a_x;
            const uint32_t kb = ((uint32_t)(kk * 32) + b_k) ^ b_x;
            uint32_t ah[4][4], al[4][4], bh[2][4], bl[2][4];
            #pragma unroll
            for (int mt = 0; mt < 4; mt++) {
                uint32_t ra = base + (uint32_t)((m0 + mt * 16 + a_r) * 128);
                LDSM4(ah[mt][0], ah[mt][1], ah[mt][2], ah[mt][3], ra + ka);
                LDSM4(al[mt][0], al[mt][1], al[mt][2], al[mt][3], ra + 16384 + ka);
            }
            #pragma unroll
            for (int p = 0; p < 2; p++) {
                uint32_t rb = base + 32768 + (uint32_t)((n0 + p * 16 + b_r) * 128);
                LDSM4(bh[p][0], bh[p][1], bh[p][2], bh[p][3], rb + kb);
                LDSM4(bl[p][0], bl[p][1], bl[p][2], bl[p][3], rb + 16384 + kb);
            }
            #pragma unroll
            for (int mt = 0; mt < 4; mt++)
                #pragma unroll
                for (int nt = 0; nt < 4; nt++) {
                    const int p = nt >> 1, hf = (nt & 1) * 2;
                    MMA_BF16(acc[mt][nt][0], acc[mt][nt][1], acc[mt][nt][2], acc[mt][nt][3],
                             ah[mt][0], ah[mt][1], ah[mt][2], ah[mt][3],
                             bh[p][hf], bh[p][hf + 1]);
                    MMA_BF16(acc[mt][nt][0], acc[mt][nt][1], acc[mt][nt][2], acc[mt][nt][3],
                             ah[mt][0], ah[mt][1], ah[mt][2], ah[mt][3],
                             bl[p][hf], bl[p][hf + 1]);
                    MMA_BF16(acc[mt][nt][0], acc[mt][nt][1], acc[mt][nt][2], acc[mt][nt][3],
                             al[mt][0], al[mt][1], al[mt][2], al[mt][3],
                             bh[p][hf], bh[p][hf + 1]);
                }
        }
        __syncthreads();
    }

    #pragma unroll
    for (int nt = 0; nt < 4; nt++) {
        const int col = nbase + n0 + nt * 8 + tig * 2;
        float2 bv = *(const float2*)&g_biasp[col];
        #pragma unroll
        for (int mt = 0; mt < 4; mt++) {
            const int row = mbase + m0 + mt * 16 + gid;
            float2 v0, v1;
            v0.x = acc[mt][nt][0] + bv.x; v0.y = acc[mt][nt][1] + bv.y;
            v1.x = acc[mt][nt][2] + bv.x; v1.y = acc[mt][nt][3] + bv.y;
            *(float2*)&g_xw[(size_t)row * FOURH + col] = v0;
            *(float2*)&g_xw[(size_t)(row + 8) * FOURH + col] = v1;
        }
    }
}

// ---------------------------------------------------------------------------
// Persistent LSTM recurrence with fine-grained producer-group flow control.
// 128 CTAs x 256 threads. CTA jb owns j' [jb*32, jb*32+32) (8 hidden x 4 gates).
// k-chunk c needs h columns [64c,64c+64) = producers CTAs [8c,8c+8): consumers
// poll g_gflag[c] >= 8*t per chunk instead of a global barrier. Chunk order is
// rotated per-CTA to decorrelate L2 traffic and flag waits.
// ---------------------------------------------------------------------------
#define PA_HI  0                 // 64KB Wh_hi slice, 16 chunks x 4KB
#define PA_LO  65536             // 64KB Wh_lo slice
#define PB     131072            // 4 stages x 16KB (h_hi 8K | h_lo 8K)
#define PXW    196608            // 8KB xw tile (64 n x 32 j')
#define PASW   204800            // 8 warps x 1152B staging
#define P_SMEM (204800 + 9216)

__global__ __launch_bounds__(256, 1)
void lstm_persistent(float* __restrict__ out) {
    extern __shared__ char smem[];
    const uint32_t sb = smem_u32(smem);
    const int tid = threadIdx.x;
    const int jb = blockIdx.x;                 // 0..127
    const int wid = tid >> 5, lane = tid & 31;
    const int n0 = wid * 8;                    // warp's batch rows
    const int gid = lane >> 2, tig = lane & 3;
    const int rot = jb >> 3;                   // chunk-order rotation = own group

    // A (Wh) ldmatrix addressing
    const int a_r = lane & 15;
    const uint32_t a_k = ((lane >> 4) & 1) * 16;
    const uint32_t a_x = (uint32_t)((a_r & 7) * 16);
    // B ldmatrix addressing (n8 x k32 via x4)
    const int b_row = lane & 7;
    const int b_mat = lane >> 3;

    // ---- load persistent Wh slice (16 k-chunks x 32 rows x 128B, hi+lo) ----
    {
        const __nv_bfloat16* Ahg = g_wht_hi + (size_t)jb * 32 * DD;
        const __nv_bfloat16* Alg = g_wht_lo + (size_t)jb * 32 * DD;
        #pragma unroll
        for (int i = 0; i < 16; i++) {
            int idx = tid + i * 256;
            int c = idx >> 8;
            int row = (idx >> 3) & 31;
            int ch = idx & 7;
            uint32_t o = (uint32_t)(c * 4096 + row * 128)
                       + (uint32_t)((ch * 16) ^ ((row & 7) * 16));
            CP16(sb + PA_HI + o, (const char*)(Ahg + (size_t)row * DD + c * 64) + ch * 16);
            CP16(sb + PA_LO + o, (const char*)(Alg + (size_t)row * DD + c * 64) + ch * 16);
        }
        CP_COMMIT();
        CP_WAIT(0);
        __syncthreads();
    }

    float creg[2] = {0.0f, 0.0f};

    for (unsigned t = 0; t < TT; t++) {
        const __nv_bfloat16* Bhg = g_h_hi[t & 1];
        const __nv_bfloat16* Blg = g_h_lo[t & 1];
        const unsigned tgt = 8u * t;

        // poll producer group for chunk c (all lanes, coalesced acquire load)
        auto wait_grp = [&](int c) {
            if (ld_acq(&g_gflag[c]) < tgt) {
                while (ld_acq(&g_gflag[c]) < tgt) { }
            }
        };

        // warp-private B chunk load: 8 rows x 64 k (hi+lo), 4 cp/lane
        auto cp_b = [&](int c, int st) {
            const int k0 = c * 64;
            const uint32_t bb = sb + PB + (uint32_t)(st * 16384);
            #pragma unroll
            for (int q = 0; q < 2; q++) {
                int idx = lane + q * 32;      // 0..63
                int row = idx >> 3;           // 0..7
                int ch = idx & 7;
                uint32_t o = (uint32_t)((n0 + row) * 128) + (uint32_t)((ch * 16) ^ (row * 16));
                CP16(bb + o,        (const char*)(Bhg + (size_t)(n0 + row) * DD + k0) + ch * 16);
                CP16(bb + 8192 + o, (const char*)(Blg + (size_t)(n0 + row) * DD + k0) + ch * 16);
            }
        };

        // group 0: warp's xw rows + B chunk (rot)
        #pragma unroll
        for (int q = 0; q < 2; q++) {
            int idx = lane + q * 32;
            int row = idx >> 3, ch = idx & 7;
            CP16(sb + PXW + (uint32_t)((n0 + row) * 128 + ch * 16),
                 (const char*)(g_xw + ((size_t)(n0 + row) * TT + t) * FOURH + jb * 32) + ch * 16);
        }
        wait_grp(rot);              cp_b(rot, 0);              CP_COMMIT();
        wait_grp((1 + rot) & 15);   cp_b((1 + rot) & 15, 1);   CP_COMMIT();
        wait_grp((2 + rot) & 15);   cp_b((2 + rot) & 15, 2);   CP_COMMIT();

        float acc[2][4];
        #pragma unroll
        for (int mt = 0; mt < 2; mt++)
            #pragma unroll
            for (int q = 0; q < 4; q++) acc[mt][q] = 0.0f;

        for (int cc = 0; cc < 16; cc++) {
            if (cc + 3 < 16) {
                const int cn = (cc + 3 + rot) & 15;
                wait_grp(cn);
                cp_b(cn, (cc + 3) & 3);
                CP_COMMIT(); CP_WAIT(3);
            }
            else if (cc == 13)   { CP_WAIT(2); }
            else if (cc == 14)   { CP_WAIT(1); }
            else                 { CP_WAIT(0); }
            __syncwarp();

            const int c = (cc + rot) & 15;
            const uint32_t bst = sb + PB + (uint32_t)((cc & 3) * 16384);
            const uint32_t ahc = sb + PA_HI + (uint32_t)(c * 4096);
            const uint32_t alc = sb + PA_LO + (uint32_t)(c * 4096);
            #pragma unroll
            for (int k2 = 0; k2 < 2; k2++) {
                uint32_t bh[4], bl[4];
                const uint32_t bo = (uint32_t)((n0 + b_row) * 128)
                                  + (uint32_t)((k2 * 64 + b_mat * 16) ^ (b_row * 16));
                LDSM4(bh[0], bh[1], bh[2], bh[3], bst + bo);
                LDSM4(bl[0], bl[1], bl[2], bl[3], bst + 8192 + bo);
                #pragma unroll
                for (int hf = 0; hf < 2; hf++) {
                    const int kk = k2 * 2 + hf;
                    const uint32_t ka = ((uint32_t)(kk * 32) + a_k) ^ a_x;
                    #pragma unroll
                    for (int mt = 0; mt < 2; mt++) {
                        uint32_t ah[4], al[4];
                        const uint32_t ao = (uint32_t)((mt * 16 + a_r) * 128) + ka;
                        LDSM4(ah[0], ah[1], ah[2], ah[3], ahc + ao);
                        LDSM4(al[0], al[1], al[2], al[3], alc + ao);
                        MMA_BF16(acc[mt][0], acc[mt][1], acc[mt][2], acc[mt][3],
                                 ah[0], ah[1], ah[2], ah[3], bh[hf * 2], bh[hf * 2 + 1]);
                        MMA_BF16(acc[mt][0], acc[mt][1], acc[mt][2], acc[mt][3],
                                 ah[0], ah[1], ah[2], ah[3], bl[hf * 2], bl[hf * 2 + 1]);
                        MMA_BF16(acc[mt][0], acc[mt][1], acc[mt][2], acc[mt][3],
                                 al[0], al[1], al[2], al[3], bh[hf * 2], bh[hf * 2 + 1]);
                    }
                }
            }
        }

        // warp-local epilogue: stage acc -> asw[n_local][j'] (stride 36), gates
        float* asw = (float*)(smem + PASW + wid * 1152);
        #pragma unroll
        for (int mt = 0; mt < 2; mt++) {
            asw[(tig * 2 + 0) * 36 + mt * 16 + gid]     = acc[mt][0];
            asw[(tig * 2 + 1) * 36 + mt * 16 + gid]     = acc[mt][1];
            asw[(tig * 2 + 0) * 36 + mt * 16 + gid + 8] = acc[mt][2];
            asw[(tig * 2 + 1) * 36 + mt * 16 + gid + 8] = acc[mt][3];
        }
        __syncwarp();

        {
            const float* xws = (const float*)(smem + PXW);
            __nv_bfloat16* nhhi = g_h_hi[(t + 1) & 1];
            __nv_bfloat16* nhlo = g_h_lo[(t + 1) & 1];
            #pragma unroll
            for (int i = 0; i < 2; i++) {
                const int p = lane + i * 32;    // 0..63
                const int nl = p >> 3;          // 0..7
                const int jhl = p & 7;          // 0..7
                const float* ar = asw + nl * 36 + jhl * 4;
                const float* xr = xws + (n0 + nl) * 32 + jhl * 4;
                float ig = fsigmoid(ar[0] + xr[0]);
                float fg = fsigmoid(ar[1] + xr[1]);
                float og = fsigmoid(ar[2] + xr[2]);
                float gg = ftanh(ar[3] + xr[3]);
                float cn = fg * creg[i] + ig * gg;
                creg[i] = cn;
                float h = og * ftanh(cn);
                const int n = n0 + nl;
                const int jg = jb * 8 + jhl;
                out[((size_t)n * TT + t) * HH + jg] = h;
                __nv_bfloat16 hh = __float2bfloat16(h);
                const int hidx = n * HH + jg;
                nhhi[hidx] = hh;
                nhlo[hidx] = __float2bfloat16(h - __bfloat162float(hh));
            }
        }

        // publish this CTA's h slice to its producer group (no global barrier)
        __syncthreads();
        if (tid == 0) {
            __threadfence();
            atomicAdd(&g_gflag[rot], 1u);
        }
    }
}

// ---------------------------------------------------------------------------
extern "C" void kernel_launch(void* const* d_in, const int* in_sizes, int n_in,
                              void* d_out, int out_size)
{
    const float* x  = (const float*)d_in[0];   // (64, 512, 1024)
    const float* h0 = (const float*)d_in[1];   // (64, 1024)
    const float* Wx = (const float*)d_in[2];   // (1024, 4096)
    const float* Wh = (const float*)d_in[3];   // (1024, 4096)
    const float* b  = (const float*)d_in[4];   // (4096,)
    float* out = (float*)d_out;                // (64, 512, 1024)

    cudaFuncSetAttribute(xw_gemm_mma,     cudaFuncAttributeMaxDynamicSharedMemorySize, G_SMEM);
    cudaFuncSetAttribute(lstm_persistent, cudaFuncAttributeMaxDynamicSharedMemorySize, P_SMEM);

    __nv_bfloat16 *wxt_hi, *wxt_lo, *wht_hi, *wht_lo;
    cudaGetSymbolAddress((void**)&wxt_hi, g_wxt_hi);
    cudaGetSymbolAddress((void**)&wxt_lo, g_wxt_lo);
    cudaGetSymbolAddress((void**)&wht_hi, g_wht_hi);
    cudaGetSymbolAddress((void**)&wht_lo, g_wht_lo);

    prep_small_kernel<<<64, 1024>>>(h0, b);
    split_x_kernel<<<(NB * TT * DD / 4) / 256, 256>>>(x);
    transpose_split_kernel<<<dim3(DD / 32, FOURH / 32), dim3(32, 8)>>>(Wx, wxt_hi, wxt_lo);
    transpose_split_kernel<<<dim3(DD / 32, FOURH / 32), dim3(32, 8)>>>(Wh, wht_hi, wht_lo);

    xw_gemm_mma<<<dim3(32, 256), 256, G_SMEM>>>();

    lstm_persistent<<<P_CTAS, 256, P_SMEM>>>(out);
}

// round 9
// speedup vs baseline: 1.2662x; 1.2662x over previous
#include <cuda_runtime.h>
#include <cuda_bf16.h>
#include <math.h>
#include <stdint.h>

#define NB 64
#define TT 512
#define DD 1024
#define HH 1024
#define FOURH 4096
#define P_CTAS 128

// ---------------------------------------------------------------------------
// Scratch (__device__ globals; allocation-free rule)
// ---------------------------------------------------------------------------
__device__ float          g_xw[(size_t)NB * TT * FOURH];      // 512 MiB xW+b (permuted cols)
__device__ __nv_bfloat16  g_xhi[(size_t)NB * TT * DD];        // 64 MiB
__device__ __nv_bfloat16  g_xlo[(size_t)NB * TT * DD];        // 64 MiB
__device__ __nv_bfloat16  g_wxt_hi[(size_t)FOURH * DD];       // WxT perm [j'][k]
__device__ __nv_bfloat16  g_wxt_lo[(size_t)FOURH * DD];
__device__ __nv_bfloat16  g_wht_hi[(size_t)FOURH * DD];       // WhT perm [j'][k]
__device__ __nv_bfloat16  g_wht_lo[(size_t)FOURH * DD];
__device__ __nv_bfloat16  g_h_hi[2][NB * HH];                 // h double buffer (bf16 hi)
__device__ __nv_bfloat16  g_h_lo[2][NB * HH];                 // h double buffer (bf16 lo)
__device__ float          g_biasp[FOURH];                     // permuted bias
__device__ unsigned       g_bar;                              // global barrier counter

// ---------------------------------------------------------------------------
// Helpers
// ---------------------------------------------------------------------------
__device__ __forceinline__ uint32_t smem_u32(const void* p) {
    uint32_t a;
    asm("{ .reg .u64 t; cvta.to.shared.u64 t, %1; cvt.u32.u64 %0, t; }"
        : "=r"(a) : "l"(p));
    return a;
}
__device__ __forceinline__ unsigned ld_acq(const unsigned* p) {
    unsigned v;
    asm volatile("ld.global.acquire.gpu.u32 %0, [%1];" : "=r"(v) : "l"(p) : "memory");
    return v;
}
__device__ __forceinline__ void red_rel_add(unsigned* p, unsigned v) {
    asm volatile("red.release.gpu.global.add.u32 [%0], %1;" :: "l"(p), "r"(v) : "memory");
}

#define CP16(dst, src) \
    asm volatile("cp.async.cg.shared.global [%0], [%1], 16;" :: "r"(dst), "l"(src) : "memory")
#define CP_COMMIT() asm volatile("cp.async.commit_group;" ::: "memory")
#define CP_WAIT(n)  asm volatile("cp.async.wait_group %0;" :: "n"(n) : "memory")

#define LDSM4(r0, r1, r2, r3, addr) \
    asm volatile("ldmatrix.sync.aligned.m8n8.x4.shared.b16 {%0,%1,%2,%3}, [%4];" \
                 : "=r"(r0), "=r"(r1), "=r"(r2), "=r"(r3) : "r"(addr))

#define MMA_BF16(c0, c1, c2, c3, a0, a1, a2, a3, b0, b1) \
    asm volatile("mma.sync.aligned.m16n8k16.row.col.f32.bf16.bf16.f32 " \
                 "{%0,%1,%2,%3}, {%4,%5,%6,%7}, {%8,%9}, {%0,%1,%2,%3};" \
                 : "+f"(c0), "+f"(c1), "+f"(c2), "+f"(c3) \
                 : "r"(a0), "r"(a1), "r"(a2), "r"(a3), "r"(b0), "r"(b1))

__device__ __forceinline__ float fsigmoid(float x) { return 1.0f / (1.0f + __expf(-x)); }
__device__ __forceinline__ float ftanh(float x)    { return 2.0f / (1.0f + __expf(-2.0f * x)) - 1.0f; }

// ---------------------------------------------------------------------------
// Prep kernels
// ---------------------------------------------------------------------------
__global__ void prep_small_kernel(const float* __restrict__ h0, const float* __restrict__ b) {
    int i = blockIdx.x * 1024 + threadIdx.x;
    if (i == 0) g_bar = 0u;
    if (i < NB * HH) {
        float v = h0[i];
        __nv_bfloat16 hi = __float2bfloat16(v);
        g_h_hi[0][i] = hi;
        g_h_lo[0][i] = __float2bfloat16(v - __bfloat162float(hi));
    }
    if (i < FOURH) {
        int jp = (i & 1023) * 4 + (i >> 10);     // perm: col g*1024+jh -> jh*4+g
        g_biasp[jp] = b[i];
    }
}

__global__ void split_x_kernel(const float* __restrict__ x) {
    size_t i = ((size_t)blockIdx.x * 256 + threadIdx.x) * 4;
    float4 v = *(const float4*)(x + i);
    __nv_bfloat16 h0 = __float2bfloat16(v.x), h1 = __float2bfloat16(v.y);
    __nv_bfloat16 h2 = __float2bfloat16(v.z), h3 = __float2bfloat16(v.w);
    __nv_bfloat162* ph = (__nv_bfloat162*)(g_xhi + i);
    __nv_bfloat162* pl = (__nv_bfloat162*)(g_xlo + i);
    ph[0] = __nv_bfloat162(h0, h1);
    ph[1] = __nv_bfloat162(h2, h3);
    pl[0] = __nv_bfloat162(__float2bfloat16(v.x - __bfloat162float(h0)),
                           __float2bfloat16(v.y - __bfloat162float(h1)));
    pl[1] = __nv_bfloat162(__float2bfloat16(v.z - __bfloat162float(h2)),
                           __float2bfloat16(v.w - __bfloat162float(h3)));
}

// W (1024 x 4096, k-major rows) -> out[j'][k] bf16 hi/lo with gate permutation.
__global__ void transpose_split_kernel(const float* __restrict__ W,
                                       __nv_bfloat16* __restrict__ ohi,
                                       __nv_bfloat16* __restrict__ olo) {
    __shared__ float ts[32][33];
    const int k0 = blockIdx.x * 32;
    const int c0 = blockIdx.y * 32;
    const int tx = threadIdx.x, ty = threadIdx.y;  // 32 x 8
    #pragma unroll
    for (int i = 0; i < 4; i++)
        ts[ty + 8 * i][tx] = W[(size_t)(k0 + ty + 8 * i) * FOURH + c0 + tx];
    __syncthreads();
    #pragma unroll
    for (int i = 0; i < 4; i++) {
        int c = c0 + ty + 8 * i;
        int jp = (c & 1023) * 4 + (c >> 10);
        float v = ts[tx][ty + 8 * i];
        __nv_bfloat16 hi = __float2bfloat16(v);
        ohi[(size_t)jp * DD + k0 + tx] = hi;
        olo[(size_t)jp * DD + k0 + tx] = __float2bfloat16(v - __bfloat162float(hi));
    }
}

// ---------------------------------------------------------------------------
// xW GEMM via mma.sync (unchanged working version)
// ---------------------------------------------------------------------------
#define G_STAGE 65536   // Ah 16K | Al 16K | Bh 16K | Bl 16K
#define G_SMEM  (3 * G_STAGE)

__global__ __launch_bounds__(256, 1)
void xw_gemm_mma() {
    extern __shared__ char smem[];
    const uint32_t sb = smem_u32(smem);
    const int tid = threadIdx.x;
    const int nbase = blockIdx.x * 128;
    const int mbase = blockIdx.y * 128;

    const __nv_bfloat16* Ahg = g_xhi + (size_t)mbase * DD;
    const __nv_bfloat16* Alg = g_xlo + (size_t)mbase * DD;
    const __nv_bfloat16* Bhg = g_wxt_hi + (size_t)nbase * DD;
    const __nv_bfloat16* Blg = g_wxt_lo + (size_t)nbase * DD;

    auto cp_chunk = [&](int c, int st) {
        const int k0 = c * 64;
        const uint32_t ah = sb + st * G_STAGE;
        #pragma unroll
        for (int i = 0; i < 4; i++) {
            int idx = tid + i * 256;
            int row = idx >> 3, ch = idx & 7;
            uint32_t o = (uint32_t)(row * 128) + (uint32_t)((ch * 16) ^ ((row & 7) * 16));
            CP16(ah + o,         (const char*)(Ahg + (size_t)row * DD + k0) + ch * 16);
            CP16(ah + 16384 + o, (const char*)(Alg + (size_t)row * DD + k0) + ch * 16);
            CP16(ah + 32768 + o, (const char*)(Bhg + (size_t)row * DD + k0) + ch * 16);
            CP16(ah + 49152 + o, (const char*)(Blg + (size_t)row * DD + k0) + ch * 16);
        }
        CP_COMMIT();
    };

    const int wid = tid >> 5, lane = tid & 31;
    const int wm = wid >> 2, wn = wid & 3;      // warp grid 2x4
    const int m0 = wm * 64, n0 = wn * 32;
    const int gid = lane >> 2, tig = lane & 3;

    const int a_r = lane & 15;
    const uint32_t a_k = ((lane >> 4) & 1) * 16;
    const uint32_t a_x = (uint32_t)((a_r & 7) * 16);
    const int b_r = (lane & 7) + ((lane >> 4) & 1) * 8;
    const uint32_t b_k = ((lane >> 3) & 1) * 16;
    const uint32_t b_x = (uint32_t)((lane & 7) * 16);

    float acc[4][4][4];
    #pragma unroll
    for (int mt = 0; mt < 4; mt++)
        #pragma unroll
        for (int nt = 0; nt < 4; nt++)
            #pragma unroll
            for (int q = 0; q < 4; q++) acc[mt][nt][q] = 0.0f;

    cp_chunk(0, 0);
    cp_chunk(1, 1);

    for (int c = 0; c < 16; c++) {
        if (c + 2 < 16) { cp_chunk(c + 2, (c + 2) % 3); CP_WAIT(2); }
        else if (c + 1 < 16) { CP_WAIT(1); }
        else { CP_WAIT(0); }
        __syncthreads();

        const uint32_t base = sb + (c % 3) * G_STAGE;
        #pragma unroll
        for (int kk = 0; kk < 4; kk++) {
            const uint32_t ka = ((uint32_t)(kk * 32) + a_k) ^ a_x;
            const uint32_t kb = ((uint32_t)(kk * 32) + b_k) ^ b_x;
            uint32_t ah[4][4], al[4][4], bh[2][4], bl[2][4];
            #pragma unroll
            for (int mt = 0; mt < 4; mt++) {
                uint32_t ra = base + (uint32_t)((m0 + mt * 16 + a_r) * 128);
                LDSM4(ah[mt][0], ah[mt][1], ah[mt][2], ah[mt][3], ra + ka);
                LDSM4(al[mt][0], al[mt][1], al[mt][2], al[mt][3], ra + 16384 + ka);
            }
            #pragma unroll
            for (int p = 0; p < 2; p++) {
                uint32_t rb = base + 32768 + (uint32_t)((n0 + p * 16 + b_r) * 128);
                LDSM4(bh[p][0], bh[p][1], bh[p][2], bh[p][3], rb + kb);
                LDSM4(bl[p][0], bl[p][1], bl[p][2], bl[p][3], rb + 16384 + kb);
            }
            #pragma unroll
            for (int mt = 0; mt < 4; mt++)
                #pragma unroll
                for (int nt = 0; nt < 4; nt++) {
                    const int p = nt >> 1, hf = (nt & 1) * 2;
                    MMA_BF16(acc[mt][nt][0], acc[mt][nt][1], acc[mt][nt][2], acc[mt][nt][3],
                             ah[mt][0], ah[mt][1], ah[mt][2], ah[mt][3],
                             bh[p][hf], bh[p][hf + 1]);
                    MMA_BF16(acc[mt][nt][0], acc[mt][nt][1], acc[mt][nt][2], acc[mt][nt][3],
                             ah[mt][0], ah[mt][1], ah[mt][2], ah[mt][3],
                             bl[p][hf], bl[p][hf + 1]);
                    MMA_BF16(acc[mt][nt][0], acc[mt][nt][1], acc[mt][nt][2], acc[mt][nt][3],
                             al[mt][0], al[mt][1], al[mt][2], al[mt][3],
                             bh[p][hf], bh[p][hf + 1]);
                }
        }
        __syncthreads();
    }

    #pragma unroll
    for (int nt = 0; nt < 4; nt++) {
        const int col = nbase + n0 + nt * 8 + tig * 2;
        float2 bv = *(const float2*)&g_biasp[col];
        #pragma unroll
        for (int mt = 0; mt < 4; mt++) {
            const int row = mbase + m0 + mt * 16 + gid;
            float2 v0, v1;
            v0.x = acc[mt][nt][0] + bv.x; v0.y = acc[mt][nt][1] + bv.y;
            v1.x = acc[mt][nt][2] + bv.x; v1.y = acc[mt][nt][3] + bv.y;
            *(float2*)&g_xw[(size_t)row * FOURH + col] = v0;
            *(float2*)&g_xw[(size_t)(row + 8) * FOURH + col] = v1;
        }
    }
}

// ---------------------------------------------------------------------------
// Persistent LSTM recurrence: warp-autonomous mainloop + rotated chunk order.
// 128 CTAs x 256 threads. CTA jb owns j' [jb*32, jb*32+32) (8 hidden x 4 gates).
// Warp w owns batch rows n in [w*8, w*8+8). One cheap global barrier per step
// (release-add publish, acquire poll). Chunk order rotated by jb>>3 to spread
// the 128-CTA h broadcast across all L2 slices instead of burst waves.
// ---------------------------------------------------------------------------
#define PA_HI  0                 // 64KB Wh_hi slice, 16 chunks x 4KB
#define PA_LO  65536             // 64KB Wh_lo slice
#define PB     131072            // 4 stages x 16KB (h_hi 8K | h_lo 8K)
#define PXW    196608            // 8KB xw tile (64 n x 32 j')
#define PASW   204800            // 8 warps x 1152B staging
#define P_SMEM (204800 + 9216)

__global__ __launch_bounds__(256, 1)
void lstm_persistent(float* __restrict__ out) {
    extern __shared__ char smem[];
    const uint32_t sb = smem_u32(smem);
    const int tid = threadIdx.x;
    const int jb = blockIdx.x;                 // 0..127
    const int wid = tid >> 5, lane = tid & 31;
    const int n0 = wid * 8;                    // warp's batch rows
    const int gid = lane >> 2, tig = lane & 3;
    const int rot = jb >> 3;                   // chunk-order rotation

    // A (Wh) ldmatrix addressing
    const int a_r = lane & 15;
    const uint32_t a_k = ((lane >> 4) & 1) * 16;
    const uint32_t a_x = (uint32_t)((a_r & 7) * 16);
    // B ldmatrix addressing (n8 x k32 via x4)
    const int b_row = lane & 7;
    const int b_mat = lane >> 3;

    // ---- load persistent Wh slice (16 k-chunks x 32 rows x 128B, hi+lo) ----
    {
        const __nv_bfloat16* Ahg = g_wht_hi + (size_t)jb * 32 * DD;
        const __nv_bfloat16* Alg = g_wht_lo + (size_t)jb * 32 * DD;
        #pragma unroll
        for (int i = 0; i < 16; i++) {
            int idx = tid + i * 256;
            int c = idx >> 8;
            int row = (idx >> 3) & 31;
            int ch = idx & 7;
            uint32_t o = (uint32_t)(c * 4096 + row * 128)
                       + (uint32_t)((ch * 16) ^ ((row & 7) * 16));
            CP16(sb + PA_HI + o, (const char*)(Ahg + (size_t)row * DD + c * 64) + ch * 16);
            CP16(sb + PA_LO + o, (const char*)(Alg + (size_t)row * DD + c * 64) + ch * 16);
        }
        CP_COMMIT();
        CP_WAIT(0);
        __syncthreads();
    }

    float creg[2] = {0.0f, 0.0f};

    for (unsigned t = 0; t < TT; t++) {
        const __nv_bfloat16* Bhg = g_h_hi[t & 1];
        const __nv_bfloat16* Blg = g_h_lo[t & 1];

        // warp-private B chunk load: 8 rows x 64 k (hi+lo), 4 cp/lane
        auto cp_b = [&](int c, int st) {
            const int k0 = c * 64;
            const uint32_t bb = sb + PB + (uint32_t)(st * 16384);
            #pragma unroll
            for (int q = 0; q < 2; q++) {
                int idx = lane + q * 32;      // 0..63
                int row = idx >> 3;           // 0..7
                int ch = idx & 7;
                uint32_t o = (uint32_t)((n0 + row) * 128) + (uint32_t)((ch * 16) ^ (row * 16));
                CP16(bb + o,        (const char*)(Bhg + (size_t)(n0 + row) * DD + k0) + ch * 16);
                CP16(bb + 8192 + o, (const char*)(Blg + (size_t)(n0 + row) * DD + k0) + ch * 16);
            }
        };

        // group 0: warp's xw rows + B chunk (rot)
        #pragma unroll
        for (int q = 0; q < 2; q++) {
            int idx = lane + q * 32;
            int row = idx >> 3, ch = idx & 7;
            CP16(sb + PXW + (uint32_t)((n0 + row) * 128 + ch * 16),
                 (const char*)(g_xw + ((size_t)(n0 + row) * TT + t) * FOURH + jb * 32) + ch * 16);
        }
        cp_b(rot, 0);              CP_COMMIT();
        cp_b((1 + rot) & 15, 1);   CP_COMMIT();
        cp_b((2 + rot) & 15, 2);   CP_COMMIT();

        float acc[2][4];
        #pragma unroll
        for (int mt = 0; mt < 2; mt++)
            #pragma unroll
            for (int q = 0; q < 4; q++) acc[mt][q] = 0.0f;

        for (int cc = 0; cc < 16; cc++) {
            if (cc + 3 < 16) {
                cp_b((cc + 3 + rot) & 15, (cc + 3) & 3);
                CP_COMMIT(); CP_WAIT(3);
            }
            else if (cc == 13)   { CP_WAIT(2); }
            else if (cc == 14)   { CP_WAIT(1); }
            else                 { CP_WAIT(0); }
            __syncwarp();

            const int c = (cc + rot) & 15;
            const uint32_t bst = sb + PB + (uint32_t)((cc & 3) * 16384);
            const uint32_t ahc = sb + PA_HI + (uint32_t)(c * 4096);
            const uint32_t alc = sb + PA_LO + (uint32_t)(c * 4096);
            #pragma unroll
            for (int k2 = 0; k2 < 2; k2++) {
                uint32_t bh[4], bl[4];
                const uint32_t bo = (uint32_t)((n0 + b_row) * 128)
                                  + (uint32_t)((k2 * 64 + b_mat * 16) ^ (b_row * 16));
                LDSM4(bh[0], bh[1], bh[2], bh[3], bst + bo);
                LDSM4(bl[0], bl[1], bl[2], bl[3], bst + 8192 + bo);
                #pragma unroll
                for (int hf = 0; hf < 2; hf++) {
                    const int kk = k2 * 2 + hf;
                    const uint32_t ka = ((uint32_t)(kk * 32) + a_k) ^ a_x;
                    #pragma unroll
                    for (int mt = 0; mt < 2; mt++) {
                        uint32_t ah[4], al[4];
                        const uint32_t ao = (uint32_t)((mt * 16 + a_r) * 128) + ka;
                        LDSM4(ah[0], ah[1], ah[2], ah[3], ahc + ao);
                        LDSM4(al[0], al[1], al[2], al[3], alc + ao);
                        MMA_BF16(acc[mt][0], acc[mt][1], acc[mt][2], acc[mt][3],
                                 ah[0], ah[1], ah[2], ah[3], bh[hf * 2], bh[hf * 2 + 1]);
                        MMA_BF16(acc[mt][0], acc[mt][1], acc[mt][2], acc[mt][3],
                                 ah[0], ah[1], ah[2], ah[3], bl[hf * 2], bl[hf * 2 + 1]);
                        MMA_BF16(acc[mt][0], acc[mt][1], acc[mt][2], acc[mt][3],
                                 al[0], al[1], al[2], al[3], bh[hf * 2], bh[hf * 2 + 1]);
                    }
                }
            }
        }

        // warp-local epilogue: stage acc -> asw[n_local][j'] (stride 36), gates
        float* asw = (float*)(smem + PASW + wid * 1152);
        #pragma unroll
        for (int mt = 0; mt < 2; mt++) {
            asw[(tig * 2 + 0) * 36 + mt * 16 + gid]     = acc[mt][0];
            asw[(tig * 2 + 1) * 36 + mt * 16 + gid]     = acc[mt][1];
            asw[(tig * 2 + 0) * 36 + mt * 16 + gid + 8] = acc[mt][2];
            asw[(tig * 2 + 1) * 36 + mt * 16 + gid + 8] = acc[mt][3];
        }
        __syncwarp();

        {
            const float* xws = (const float*)(smem + PXW);
            __nv_bfloat16* nhhi = g_h_hi[(t + 1) & 1];
            __nv_bfloat16* nhlo = g_h_lo[(t + 1) & 1];
            #pragma unroll
            for (int i = 0; i < 2; i++) {
                const int p = lane + i * 32;    // 0..63
                const int nl = p >> 3;          // 0..7
                const int jhl = p & 7;          // 0..7
                const float* ar = asw + nl * 36 + jhl * 4;
                const float* xr = xws + (n0 + nl) * 32 + jhl * 4;
                float ig = fsigmoid(ar[0] + xr[0]);
                float fg = fsigmoid(ar[1] + xr[1]);
                float og = fsigmoid(ar[2] + xr[2]);
                float gg = ftanh(ar[3] + xr[3]);
                float cn = fg * creg[i] + ig * gg;
                creg[i] = cn;
                float h = og * ftanh(cn);
                const int n = n0 + nl;
                const int jg = jb * 8 + jhl;
                out[((size_t)n * TT + t) * HH + jg] = h;
                __nv_bfloat16 hh = __float2bfloat16(h);
                const int hidx = n * HH + jg;
                nhhi[hidx] = hh;
                nhlo[hidx] = __float2bfloat16(h - __bfloat162float(hh));
            }
        }

        // cheap global barrier: release-add publish, acquire poll (tid 0 only)
        __syncthreads();
        if (tid == 0) {
            red_rel_add(&g_bar, 1u);
            const unsigned target = (t + 1u) * (unsigned)P_CTAS;
            while (ld_acq(&g_bar) < target) { }
        }
        __syncthreads();
    }
}

// ---------------------------------------------------------------------------
extern "C" void kernel_launch(void* const* d_in, const int* in_sizes, int n_in,
                              void* d_out, int out_size)
{
    const float* x  = (const float*)d_in[0];   // (64, 512, 1024)
    const float* h0 = (const float*)d_in[1];   // (64, 1024)
    const float* Wx = (const float*)d_in[2];   // (1024, 4096)
    const float* Wh = (const float*)d_in[3];   // (1024, 4096)
    const float* b  = (const float*)d_in[4];   // (4096,)
    float* out = (float*)d_out;                // (64, 512, 1024)

    cudaFuncSetAttribute(xw_gemm_mma,     cudaFuncAttributeMaxDynamicSharedMemorySize, G_SMEM);
    cudaFuncSetAttribute(lstm_persistent, cudaFuncAttributeMaxDynamicSharedMemorySize, P_SMEM);

    __nv_bfloat16 *wxt_hi, *wxt_lo, *wht_hi, *wht_lo;
    cudaGetSymbolAddress((void**)&wxt_hi, g_wxt_hi);
    cudaGetSymbolAddress((void**)&wxt_lo, g_wxt_lo);
    cudaGetSymbolAddress((void**)&wht_hi, g_wht_hi);
    cudaGetSymbolAddress((void**)&wht_lo, g_wht_lo);

    prep_small_kernel<<<64, 1024>>>(h0, b);
    split_x_kernel<<<(NB * TT * DD / 4) / 256, 256>>>(x);
    transpose_split_kernel<<<dim3(DD / 32, FOURH / 32), dim3(32, 8)>>>(Wx, wxt_hi, wxt_lo);
    transpose_split_kernel<<<dim3(DD / 32, FOURH / 32), dim3(32, 8)>>>(Wh, wht_hi, wht_lo);

    xw_gemm_mma<<<dim3(32, 256), 256, G_SMEM>>>();

    lstm_persistent<<<P_CTAS, 256, P_SMEM>>>(out);
}

// round 10
// speedup vs baseline: 1.2680x; 1.0014x over previous
#include <cuda_runtime.h>
#include <cuda_bf16.h>
#include <math.h>
#include <stdint.h>

#define NB 64
#define TT 512
#define DD 1024
#define HH 1024
#define FOURH 4096
#define P_CTAS 128

// ---------------------------------------------------------------------------
// Scratch (__device__ globals; allocation-free rule)
// ---------------------------------------------------------------------------
__device__ float          g_xw[(size_t)NB * TT * FOURH];      // 512 MiB xW+b (permuted cols)
__device__ __nv_bfloat16  g_xhi[(size_t)NB * TT * DD];        // 64 MiB
__device__ __nv_bfloat16  g_xlo[(size_t)NB * TT * DD];        // 64 MiB
__device__ __nv_bfloat16  g_wxt_hi[(size_t)FOURH * DD];       // WxT perm [j'][k]
__device__ __nv_bfloat16  g_wxt_lo[(size_t)FOURH * DD];
__device__ __nv_bfloat16  g_wht_hi[(size_t)FOURH * DD];       // WhT perm [j'][k]
__device__ __nv_bfloat16  g_wht_lo[(size_t)FOURH * DD];
__device__ __nv_bfloat16  g_h_hi[2][NB * HH];                 // h double buffer (bf16 hi)
__device__ __nv_bfloat16  g_h_lo[2][NB * HH];                 // h double buffer (bf16 lo)
__device__ float          g_biasp[FOURH];                     // permuted bias
__device__ unsigned       g_bar;                              // global barrier counter

// ---------------------------------------------------------------------------
// Helpers
// ---------------------------------------------------------------------------
__device__ __forceinline__ uint32_t smem_u32(const void* p) {
    uint32_t a;
    asm("{ .reg .u64 t; cvta.to.shared.u64 t, %1; cvt.u32.u64 %0, t; }"
        : "=r"(a) : "l"(p));
    return a;
}
__device__ __forceinline__ unsigned ld_acq(const unsigned* p) {
    unsigned v;
    asm volatile("ld.global.acquire.gpu.u32 %0, [%1];" : "=r"(v) : "l"(p) : "memory");
    return v;
}
__device__ __forceinline__ void red_rel_add(unsigned* p, unsigned v) {
    asm volatile("red.release.gpu.global.add.u32 [%0], %1;" :: "l"(p), "r"(v) : "memory");
}

#define CP16(dst, src) \
    asm volatile("cp.async.cg.shared.global [%0], [%1], 16;" :: "r"(dst), "l"(src) : "memory")
#define CP_COMMIT() asm volatile("cp.async.commit_group;" ::: "memory")
#define CP_WAIT(n)  asm volatile("cp.async.wait_group %0;" :: "n"(n) : "memory")

#define LDSM4(r0, r1, r2, r3, addr) \
    asm volatile("ldmatrix.sync.aligned.m8n8.x4.shared.b16 {%0,%1,%2,%3}, [%4];" \
                 : "=r"(r0), "=r"(r1), "=r"(r2), "=r"(r3) : "r"(addr))

#define MMA_BF16(c0, c1, c2, c3, a0, a1, a2, a3, b0, b1) \
    asm volatile("mma.sync.aligned.m16n8k16.row.col.f32.bf16.bf16.f32 " \
                 "{%0,%1,%2,%3}, {%4,%5,%6,%7}, {%8,%9}, {%0,%1,%2,%3};" \
                 : "+f"(c0), "+f"(c1), "+f"(c2), "+f"(c3) \
                 : "r"(a0), "r"(a1), "r"(a2), "r"(a3), "r"(b0), "r"(b1))

__device__ __forceinline__ float fsigmoid(float x) { return 1.0f / (1.0f + __expf(-x)); }
__device__ __forceinline__ float ftanh(float x)    { return 2.0f / (1.0f + __expf(-2.0f * x)) - 1.0f; }

// ---------------------------------------------------------------------------
// Prep kernels
// ---------------------------------------------------------------------------
__global__ void prep_small_kernel(const float* __restrict__ h0, const float* __restrict__ b) {
    int i = blockIdx.x * 1024 + threadIdx.x;
    if (i == 0) g_bar = 0u;
    if (i < NB * HH) {
        float v = h0[i];
        __nv_bfloat16 hi = __float2bfloat16(v);
        g_h_hi[0][i] = hi;
        g_h_lo[0][i] = __float2bfloat16(v - __bfloat162float(hi));
    }
    if (i < FOURH) {
        int jp = (i & 1023) * 4 + (i >> 10);     // perm: col g*1024+jh -> jh*4+g
        g_biasp[jp] = b[i];
    }
}

__global__ void split_x_kernel(const float* __restrict__ x) {
    size_t i = ((size_t)blockIdx.x * 256 + threadIdx.x) * 4;
    float4 v = *(const float4*)(x + i);
    __nv_bfloat16 h0 = __float2bfloat16(v.x), h1 = __float2bfloat16(v.y);
    __nv_bfloat16 h2 = __float2bfloat16(v.z), h3 = __float2bfloat16(v.w);
    __nv_bfloat162* ph = (__nv_bfloat162*)(g_xhi + i);
    __nv_bfloat162* pl = (__nv_bfloat162*)(g_xlo + i);
    ph[0] = __nv_bfloat162(h0, h1);
    ph[1] = __nv_bfloat162(h2, h3);
    pl[0] = __nv_bfloat162(__float2bfloat16(v.x - __bfloat162float(h0)),
                           __float2bfloat16(v.y - __bfloat162float(h1)));
    pl[1] = __nv_bfloat162(__float2bfloat16(v.z - __bfloat162float(h2)),
                           __float2bfloat16(v.w - __bfloat162float(h3)));
}

// W (1024 x 4096, k-major rows) -> out[j'][k] bf16 hi/lo with gate permutation.
__global__ void transpose_split_kernel(const float* __restrict__ W,
                                       __nv_bfloat16* __restrict__ ohi,
                                       __nv_bfloat16* __restrict__ olo) {
    __shared__ float ts[32][33];
    const int k0 = blockIdx.x * 32;
    const int c0 = blockIdx.y * 32;
    const int tx = threadIdx.x, ty = threadIdx.y;  // 32 x 8
    #pragma unroll
    for (int i = 0; i < 4; i++)
        ts[ty + 8 * i][tx] = W[(size_t)(k0 + ty + 8 * i) * FOURH + c0 + tx];
    __syncthreads();
    #pragma unroll
    for (int i = 0; i < 4; i++) {
        int c = c0 + ty + 8 * i;
        int jp = (c & 1023) * 4 + (c >> 10);
        float v = ts[tx][ty + 8 * i];
        __nv_bfloat16 hi = __float2bfloat16(v);
        ohi[(size_t)jp * DD + k0 + tx] = hi;
        olo[(size_t)jp * DD + k0 + tx] = __float2bfloat16(v - __bfloat162float(hi));
    }
}

// ---------------------------------------------------------------------------
// xW GEMM via mma.sync (unchanged working version)
// ---------------------------------------------------------------------------
#define G_STAGE 65536   // Ah 16K | Al 16K | Bh 16K | Bl 16K
#define G_SMEM  (3 * G_STAGE)

__global__ __launch_bounds__(256, 1)
void xw_gemm_mma() {
    extern __shared__ char smem[];
    const uint32_t sb = smem_u32(smem);
    const int tid = threadIdx.x;
    const int nbase = blockIdx.x * 128;
    const int mbase = blockIdx.y * 128;

    const __nv_bfloat16* Ahg = g_xhi + (size_t)mbase * DD;
    const __nv_bfloat16* Alg = g_xlo + (size_t)mbase * DD;
    const __nv_bfloat16* Bhg = g_wxt_hi + (size_t)nbase * DD;
    const __nv_bfloat16* Blg = g_wxt_lo + (size_t)nbase * DD;

    auto cp_chunk = [&](int c, int st) {
        const int k0 = c * 64;
        const uint32_t ah = sb + st * G_STAGE;
        #pragma unroll
        for (int i = 0; i < 4; i++) {
            int idx = tid + i * 256;
            int row = idx >> 3, ch = idx & 7;
            uint32_t o = (uint32_t)(row * 128) + (uint32_t)((ch * 16) ^ ((row & 7) * 16));
            CP16(ah + o,         (const char*)(Ahg + (size_t)row * DD + k0) + ch * 16);
            CP16(ah + 16384 + o, (const char*)(Alg + (size_t)row * DD + k0) + ch * 16);
            CP16(ah + 32768 + o, (const char*)(Bhg + (size_t)row * DD + k0) + ch * 16);
            CP16(ah + 49152 + o, (const char*)(Blg + (size_t)row * DD + k0) + ch * 16);
        }
        CP_COMMIT();
    };

    const int wid = tid >> 5, lane = tid & 31;
    const int wm = wid >> 2, wn = wid & 3;      // warp grid 2x4
    const int m0 = wm * 64, n0 = wn * 32;
    const int gid = lane >> 2, tig = lane & 3;

    const int a_r = lane & 15;
    const uint32_t a_k = ((lane >> 4) & 1) * 16;
    const uint32_t a_x = (uint32_t)((a_r & 7) * 16);
    const int b_r = (lane & 7) + ((lane >> 4) & 1) * 8;
    const uint32_t b_k = ((lane >> 3) & 1) * 16;
    const uint32_t b_x = (uint32_t)((lane & 7) * 16);

    float acc[4][4][4];
    #pragma unroll
    for (int mt = 0; mt < 4; mt++)
        #pragma unroll
        for (int nt = 0; nt < 4; nt++)
            #pragma unroll
            for (int q = 0; q < 4; q++) acc[mt][nt][q] = 0.0f;

    cp_chunk(0, 0);
    cp_chunk(1, 1);

    for (int c = 0; c < 16; c++) {
        if (c + 2 < 16) { cp_chunk(c + 2, (c + 2) % 3); CP_WAIT(2); }
        else if (c + 1 < 16) { CP_WAIT(1); }
        else { CP_WAIT(0); }
        __syncthreads();

        const uint32_t base = sb + (c % 3) * G_STAGE;
        #pragma unroll
        for (int kk = 0; kk < 4; kk++) {
            const uint32_t ka = ((uint32_t)(kk * 32) + a_k) ^ a_x;
            const uint32_t kb = ((uint32_t)(kk * 32) + b_k) ^ b_x;
            uint32_t ah[4][4], al[4][4], bh[2][4], bl[2][4];
            #pragma unroll
            for (int mt = 0; mt < 4; mt++) {
                uint32_t ra = base + (uint32_t)((m0 + mt * 16 + a_r) * 128);
                LDSM4(ah[mt][0], ah[mt][1], ah[mt][2], ah[mt][3], ra + ka);
                LDSM4(al[mt][0], al[mt][1], al[mt][2], al[mt][3], ra + 16384 + ka);
            }
            #pragma unroll
            for (int p = 0; p < 2; p++) {
                uint32_t rb = base + 32768 + (uint32_t)((n0 + p * 16 + b_r) * 128);
                LDSM4(bh[p][0], bh[p][1], bh[p][2], bh[p][3], rb + kb);
                LDSM4(bl[p][0], bl[p][1], bl[p][2], bl[p][3], rb + 16384 + kb);
            }
            #pragma unroll
            for (int mt = 0; mt < 4; mt++)
                #pragma unroll
                for (int nt = 0; nt < 4; nt++) {
                    const int p = nt >> 1, hf = (nt & 1) * 2;
                    MMA_BF16(acc[mt][nt][0], acc[mt][nt][1], acc[mt][nt][2], acc[mt][nt][3],
                             ah[mt][0], ah[mt][1], ah[mt][2], ah[mt][3],
                             bh[p][hf], bh[p][hf + 1]);
                    MMA_BF16(acc[mt][nt][0], acc[mt][nt][1], acc[mt][nt][2], acc[mt][nt][3],
                             ah[mt][0], ah[mt][1], ah[mt][2], ah[mt][3],
                             bl[p][hf], bl[p][hf + 1]);
                    MMA_BF16(acc[mt][nt][0], acc[mt][nt][1], acc[mt][nt][2], acc[mt][nt][3],
                             al[mt][0], al[mt][1], al[mt][2], al[mt][3],
                             bh[p][hf], bh[p][hf + 1]);
                }
        }
        __syncthreads();
    }

    #pragma unroll
    for (int nt = 0; nt < 4; nt++) {
        const int col = nbase + n0 + nt * 8 + tig * 2;
        float2 bv = *(const float2*)&g_biasp[col];
        #pragma unroll
        for (int mt = 0; mt < 4; mt++) {
            const int row = mbase + m0 + mt * 16 + gid;
            float2 v0, v1;
            v0.x = acc[mt][nt][0] + bv.x; v0.y = acc[mt][nt][1] + bv.y;
            v1.x = acc[mt][nt][2] + bv.x; v1.y = acc[mt][nt][3] + bv.y;
            *(float2*)&g_xw[(size_t)row * FOURH + col] = v0;
            *(float2*)&g_xw[(size_t)(row + 8) * FOURH + col] = v1;
        }
    }
}

// ---------------------------------------------------------------------------
// Persistent LSTM recurrence: warp-autonomous mainloop + rotated chunk order.
// 128 CTAs x 256 threads. CTA jb owns j' [jb*32, jb*32+32) (8 hidden x 4 gates).
// Warp w owns batch rows n in [w*8, w*8+8). One cheap global barrier per step
// (release-add publish, acquire poll). Chunk order rotated by jb>>3 to spread
// the 128-CTA h broadcast across all L2 slices instead of burst waves.
// ---------------------------------------------------------------------------
#define PA_HI  0                 // 64KB Wh_hi slice, 16 chunks x 4KB
#define PA_LO  65536             // 64KB Wh_lo slice
#define PB     131072            // 4 stages x 16KB (h_hi 8K | h_lo 8K)
#define PXW    196608            // 8KB xw tile (64 n x 32 j')
#define PASW   204800            // 8 warps x 1152B staging
#define P_SMEM (204800 + 9216)

__global__ __launch_bounds__(256, 1)
void lstm_persistent(float* __restrict__ out) {
    extern __shared__ char smem[];
    const uint32_t sb = smem_u32(smem);
    const int tid = threadIdx.x;
    const int jb = blockIdx.x;                 // 0..127
    const int wid = tid >> 5, lane = tid & 31;
    const int n0 = wid * 8;                    // warp's batch rows
    const int gid = lane >> 2, tig = lane & 3;
    const int rot = jb >> 3;                   // chunk-order rotation

    // A (Wh) ldmatrix addressing
    const int a_r = lane & 15;
    const uint32_t a_k = ((lane >> 4) & 1) * 16;
    const uint32_t a_x = (uint32_t)((a_r & 7) * 16);
    // B ldmatrix addressing (n8 x k32 via x4)
    const int b_row = lane & 7;
    const int b_mat = lane >> 3;

    // ---- load persistent Wh slice (16 k-chunks x 32 rows x 128B, hi+lo) ----
    {
        const __nv_bfloat16* Ahg = g_wht_hi + (size_t)jb * 32 * DD;
        const __nv_bfloat16* Alg = g_wht_lo + (size_t)jb * 32 * DD;
        #pragma unroll
        for (int i = 0; i < 16; i++) {
            int idx = tid + i * 256;
            int c = idx >> 8;
            int row = (idx >> 3) & 31;
            int ch = idx & 7;
            uint32_t o = (uint32_t)(c * 4096 + row * 128)
                       + (uint32_t)((ch * 16) ^ ((row & 7) * 16));
            CP16(sb + PA_HI + o, (const char*)(Ahg + (size_t)row * DD + c * 64) + ch * 16);
            CP16(sb + PA_LO + o, (const char*)(Alg + (size_t)row * DD + c * 64) + ch * 16);
        }
        CP_COMMIT();
        CP_WAIT(0);
        __syncthreads();
    }

    float creg[2] = {0.0f, 0.0f};

    for (unsigned t = 0; t < TT; t++) {
        const __nv_bfloat16* Bhg = g_h_hi[t & 1];
        const __nv_bfloat16* Blg = g_h_lo[t & 1];

        // warp-private B chunk load: 8 rows x 64 k (hi+lo), 4 cp/lane
        auto cp_b = [&](int c, int st) {
            const int k0 = c * 64;
            const uint32_t bb = sb + PB + (uint32_t)(st * 16384);
            #pragma unroll
            for (int q = 0; q < 2; q++) {
                int idx = lane + q * 32;      // 0..63
                int row = idx >> 3;           // 0..7
                int ch = idx & 7;
                uint32_t o = (uint32_t)((n0 + row) * 128) + (uint32_t)((ch * 16) ^ (row * 16));
                CP16(bb + o,        (const char*)(Bhg + (size_t)(n0 + row) * DD + k0) + ch * 16);
                CP16(bb + 8192 + o, (const char*)(Blg + (size_t)(n0 + row) * DD + k0) + ch * 16);
            }
        };

        // group 0: warp's xw rows + B chunk (rot)
        #pragma unroll
        for (int q = 0; q < 2; q++) {
            int idx = lane + q * 32;
            int row = idx >> 3, ch = idx & 7;
            CP16(sb + PXW + (uint32_t)((n0 + row) * 128 + ch * 16),
                 (const char*)(g_xw + ((size_t)(n0 + row) * TT + t) * FOURH + jb * 32) + ch * 16);
        }
        cp_b(rot, 0);              CP_COMMIT();
        cp_b((1 + rot) & 15, 1);   CP_COMMIT();
        cp_b((2 + rot) & 15, 2);   CP_COMMIT();

        float acc[2][4];
        #pragma unroll
        for (int mt = 0; mt < 2; mt++)
            #pragma unroll
            for (int q = 0; q < 4; q++) acc[mt][q] = 0.0f;

        for (int cc = 0; cc < 16; cc++) {
            if (cc + 3 < 16) {
                cp_b((cc + 3 + rot) & 15, (cc + 3) & 3);
                CP_COMMIT(); CP_WAIT(3);
            }
            else if (cc == 13)   { CP_WAIT(2); }
            else if (cc == 14)   { CP_WAIT(1); }
            else                 { CP_WAIT(0); }
            __syncwarp();

            const int c = (cc + rot) & 15;
            const uint32_t bst = sb + PB + (uint32_t)((cc & 3) * 16384);
            const uint32_t ahc = sb + PA_HI + (uint32_t)(c * 4096);
            const uint32_t alc = sb + PA_LO + (uint32_t)(c * 4096);
            #pragma unroll
            for (int k2 = 0; k2 < 2; k2++) {
                uint32_t bh[4], bl[4];
                const uint32_t bo = (uint32_t)((n0 + b_row) * 128)
                                  + (uint32_t)((k2 * 64 + b_mat * 16) ^ (b_row * 16));
                LDSM4(bh[0], bh[1], bh[2], bh[3], bst + bo);
                LDSM4(bl[0], bl[1], bl[2], bl[3], bst + 8192 + bo);
                #pragma unroll
                for (int hf = 0; hf < 2; hf++) {
                    const int kk = k2 * 2 + hf;
                    const uint32_t ka = ((uint32_t)(kk * 32) + a_k) ^ a_x;
                    #pragma unroll
                    for (int mt = 0; mt < 2; mt++) {
                        uint32_t ah[4], al[4];
                        const uint32_t ao = (uint32_t)((mt * 16 + a_r) * 128) + ka;
                        LDSM4(ah[0], ah[1], ah[2], ah[3], ahc + ao);
                        LDSM4(al[0], al[1], al[2], al[3], alc + ao);
                        MMA_BF16(acc[mt][0], acc[mt][1], acc[mt][2], acc[mt][3],
                                 ah[0], ah[1], ah[2], ah[3], bh[hf * 2], bh[hf * 2 + 1]);
                        MMA_BF16(acc[mt][0], acc[mt][1], acc[mt][2], acc[mt][3],
                                 ah[0], ah[1], ah[2], ah[3], bl[hf * 2], bl[hf * 2 + 1]);
                        MMA_BF16(acc[mt][0], acc[mt][1], acc[mt][2], acc[mt][3],
                                 al[0], al[1], al[2], al[3], bh[hf * 2], bh[hf * 2 + 1]);
                    }
                }
            }
        }

        // warp-local epilogue: stage acc -> asw[n_local][j'] (stride 36), gates
        float* asw = (float*)(smem + PASW + wid * 1152);
        #pragma unroll
        for (int mt = 0; mt < 2; mt++) {
            asw[(tig * 2 + 0) * 36 + mt * 16 + gid]     = acc[mt][0];
            asw[(tig * 2 + 1) * 36 + mt * 16 + gid]     = acc[mt][1];
            asw[(tig * 2 + 0) * 36 + mt * 16 + gid + 8] = acc[mt][2];
            asw[(tig * 2 + 1) * 36 + mt * 16 + gid + 8] = acc[mt][3];
        }
        __syncwarp();

        {
            const float* xws = (const float*)(smem + PXW);
            __nv_bfloat16* nhhi = g_h_hi[(t + 1) & 1];
            __nv_bfloat16* nhlo = g_h_lo[(t + 1) & 1];
            #pragma unroll
            for (int i = 0; i < 2; i++) {
                const int p = lane + i * 32;    // 0..63
                const int nl = p >> 3;          // 0..7
                const int jhl = p & 7;          // 0..7
                const float* ar = asw + nl * 36 + jhl * 4;
                const float* xr = xws + (n0 + nl) * 32 + jhl * 4;
                float ig = fsigmoid(ar[0] + xr[0]);
                float fg = fsigmoid(ar[1] + xr[1]);
                float og = fsigmoid(ar[2] + xr[2]);
                float gg = ftanh(ar[3] + xr[3]);
                float cn = fg * creg[i] + ig * gg;
                creg[i] = cn;
                float h = og * ftanh(cn);
                const int n = n0 + nl;
                const int jg = jb * 8 + jhl;
                out[((size_t)n * TT + t) * HH + jg] = h;
                __nv_bfloat16 hh = __float2bfloat16(h);
                const int hidx = n * HH + jg;
                nhhi[hidx] = hh;
                nhlo[hidx] = __float2bfloat16(h - __bfloat162float(hh));
            }
        }

        // cheap global barrier: release-add publish, acquire poll (tid 0 only)
        __syncthreads();
        if (tid == 0) {
            red_rel_add(&g_bar, 1u);
            const unsigned target = (t + 1u) * (unsigned)P_CTAS;
            while (ld_acq(&g_bar) < target) { }
        }
        __syncthreads();
    }
}

// ---------------------------------------------------------------------------
extern "C" void kernel_launch(void* const* d_in, const int* in_sizes, int n_in,
                              void* d_out, int out_size)
{
    const float* x  = (const float*)d_in[0];   // (64, 512, 1024)
    const float* h0 = (const float*)d_in[1];   // (64, 1024)
    const float* Wx = (const float*)d_in[2];   // (1024, 4096)
    const float* Wh = (const float*)d_in[3];   // (1024, 4096)
    const float* b  = (const float*)d_in[4];   // (4096,)
    float* out = (float*)d_out;                // (64, 512, 1024)

    cudaFuncSetAttribute(xw_gemm_mma,     cudaFuncAttributeMaxDynamicSharedMemorySize, G_SMEM);
    cudaFuncSetAttribute(lstm_persistent, cudaFuncAttributeMaxDynamicSharedMemorySize, P_SMEM);

    __nv_bfloat16 *wxt_hi, *wxt_lo, *wht_hi, *wht_lo;
    cudaGetSymbolAddress((void**)&wxt_hi, g_wxt_hi);
    cudaGetSymbolAddress((void**)&wxt_lo, g_wxt_lo);
    cudaGetSymbolAddress((void**)&wht_hi, g_wht_hi);
    cudaGetSymbolAddress((void**)&wht_lo, g_wht_lo);

    prep_small_kernel<<<64, 1024>>>(h0, b);
    split_x_kernel<<<(NB * TT * DD / 4) / 256, 256>>>(x);
    transpose_split_kernel<<<dim3(DD / 32, FOURH / 32), dim3(32, 8)>>>(Wx, wxt_hi, wxt_lo);
    transpose_split_kernel<<<dim3(DD / 32, FOURH / 32), dim3(32, 8)>>>(Wh, wht_hi, wht_lo);

    xw_gemm_mma<<<dim3(32, 256), 256, G_SMEM>>>();

    lstm_persistent<<<P_CTAS, 256, P_SMEM>>>(out);
}

// round 11
// speedup vs baseline: 1.2694x; 1.0011x over previous
#include <cuda_runtime.h>
#include <cuda_bf16.h>
#include <math.h>
#include <stdint.h>

#define NB 64
#define TT 512
#define DD 1024
#define HH 1024
#define FOURH 4096
#define P_CTAS 128

// ---------------------------------------------------------------------------
// Scratch (__device__ globals; allocation-free rule)
// ---------------------------------------------------------------------------
__device__ float          g_xw[(size_t)NB * TT * FOURH];      // 512 MiB xW+b (permuted cols)
__device__ __nv_bfloat16  g_xhi[(size_t)NB * TT * DD];        // 64 MiB
__device__ __nv_bfloat16  g_xlo[(size_t)NB * TT * DD];        // 64 MiB
__device__ __nv_bfloat16  g_wxt_hi[(size_t)FOURH * DD];       // WxT perm [j'][k]
__device__ __nv_bfloat16  g_wxt_lo[(size_t)FOURH * DD];
__device__ __nv_bfloat16  g_wht_hi[(size_t)FOURH * DD];       // WhT perm [j'][k]
__device__ __nv_bfloat16  g_wht_lo[(size_t)FOURH * DD];
__device__ __nv_bfloat16  g_h_hi[2][NB * HH];                 // h double buffer (bf16 hi)
__device__ __nv_bfloat16  g_h_lo[2][NB * HH];                 // h double buffer (bf16 lo)
__device__ float          g_biasp[FOURH];                     // permuted bias
__device__ unsigned       g_bar;                              // global barrier counter

// ---------------------------------------------------------------------------
// Helpers
// ---------------------------------------------------------------------------
__device__ __forceinline__ uint32_t smem_u32(const void* p) {
    uint32_t a;
    asm("{ .reg .u64 t; cvta.to.shared.u64 t, %1; cvt.u32.u64 %0, t; }"
        : "=r"(a) : "l"(p));
    return a;
}
__device__ __forceinline__ unsigned ld_acq(const unsigned* p) {
    unsigned v;
    asm volatile("ld.global.acquire.gpu.u32 %0, [%1];" : "=r"(v) : "l"(p) : "memory");
    return v;
}
__device__ __forceinline__ void red_rel_add(unsigned* p, unsigned v) {
    asm volatile("red.release.gpu.global.add.u32 [%0], %1;" :: "l"(p), "r"(v) : "memory");
}

#define CP16(dst, src) \
    asm volatile("cp.async.cg.shared.global [%0], [%1], 16;" :: "r"(dst), "l"(src) : "memory")
#define CP_COMMIT() asm volatile("cp.async.commit_group;" ::: "memory")
#define CP_WAIT(n)  asm volatile("cp.async.wait_group %0;" :: "n"(n) : "memory")

#define LDSM4(r0, r1, r2, r3, addr) \
    asm volatile("ldmatrix.sync.aligned.m8n8.x4.shared.b16 {%0,%1,%2,%3}, [%4];" \
                 : "=r"(r0), "=r"(r1), "=r"(r2), "=r"(r3) : "r"(addr))

#define MMA_BF16(c0, c1, c2, c3, a0, a1, a2, a3, b0, b1) \
    asm volatile("mma.sync.aligned.m16n8k16.row.col.f32.bf16.bf16.f32 " \
                 "{%0,%1,%2,%3}, {%4,%5,%6,%7}, {%8,%9}, {%0,%1,%2,%3};" \
                 : "+f"(c0), "+f"(c1), "+f"(c2), "+f"(c3) \
                 : "r"(a0), "r"(a1), "r"(a2), "r"(a3), "r"(b0), "r"(b1))

__device__ __forceinline__ float fsigmoid(float x) { return 1.0f / (1.0f + __expf(-x)); }
__device__ __forceinline__ float ftanh(float x)    { return 2.0f / (1.0f + __expf(-2.0f * x)) - 1.0f; }

// ---------------------------------------------------------------------------
// Prep kernels
// ---------------------------------------------------------------------------
__global__ void prep_small_kernel(const float* __restrict__ h0, const float* __restrict__ b) {
    int i = blockIdx.x * 1024 + threadIdx.x;
    if (i == 0) g_bar = 0u;
    if (i < NB * HH) {
        float v = h0[i];
        __nv_bfloat16 hi = __float2bfloat16(v);
        g_h_hi[0][i] = hi;
        g_h_lo[0][i] = __float2bfloat16(v - __bfloat162float(hi));
    }
    if (i < FOURH) {
        int jp = (i & 1023) * 4 + (i >> 10);     // perm: col g*1024+jh -> jh*4+g
        g_biasp[jp] = b[i];
    }
}

__global__ void split_x_kernel(const float* __restrict__ x) {
    size_t i = ((size_t)blockIdx.x * 256 + threadIdx.x) * 4;
    float4 v = *(const float4*)(x + i);
    __nv_bfloat16 h0 = __float2bfloat16(v.x), h1 = __float2bfloat16(v.y);
    __nv_bfloat16 h2 = __float2bfloat16(v.z), h3 = __float2bfloat16(v.w);
    __nv_bfloat162* ph = (__nv_bfloat162*)(g_xhi + i);
    __nv_bfloat162* pl = (__nv_bfloat162*)(g_xlo + i);
    ph[0] = __nv_bfloat162(h0, h1);
    ph[1] = __nv_bfloat162(h2, h3);
    pl[0] = __nv_bfloat162(__float2bfloat16(v.x - __bfloat162float(h0)),
                           __float2bfloat16(v.y - __bfloat162float(h1)));
    pl[1] = __nv_bfloat162(__float2bfloat16(v.z - __bfloat162float(h2)),
                           __float2bfloat16(v.w - __bfloat162float(h3)));
}

// W (1024 x 4096, k-major rows) -> out[j'][k] bf16 hi/lo with gate permutation.
__global__ void transpose_split_kernel(const float* __restrict__ W,
                                       __nv_bfloat16* __restrict__ ohi,
                                       __nv_bfloat16* __restrict__ olo) {
    __shared__ float ts[32][33];
    const int k0 = blockIdx.x * 32;
    const int c0 = blockIdx.y * 32;
    const int tx = threadIdx.x, ty = threadIdx.y;  // 32 x 8
    #pragma unroll
    for (int i = 0; i < 4; i++)
        ts[ty + 8 * i][tx] = W[(size_t)(k0 + ty + 8 * i) * FOURH + c0 + tx];
    __syncthreads();
    #pragma unroll
    for (int i = 0; i < 4; i++) {
        int c = c0 + ty + 8 * i;
        int jp = (c & 1023) * 4 + (c >> 10);
        float v = ts[tx][ty + 8 * i];
        __nv_bfloat16 hi = __float2bfloat16(v);
        ohi[(size_t)jp * DD + k0 + tx] = hi;
        olo[(size_t)jp * DD + k0 + tx] = __float2bfloat16(v - __bfloat162float(hi));
    }
}

// ---------------------------------------------------------------------------
// xW GEMM via mma.sync (unchanged working version)
// ---------------------------------------------------------------------------
#define G_STAGE 65536   // Ah 16K | Al 16K | Bh 16K | Bl 16K
#define G_SMEM  (3 * G_STAGE)

__global__ __launch_bounds__(256, 1)
void xw_gemm_mma() {
    extern __shared__ char smem[];
    const uint32_t sb = smem_u32(smem);
    const int tid = threadIdx.x;
    const int nbase = blockIdx.x * 128;
    const int mbase = blockIdx.y * 128;

    const __nv_bfloat16* Ahg = g_xhi + (size_t)mbase * DD;
    const __nv_bfloat16* Alg = g_xlo + (size_t)mbase * DD;
    const __nv_bfloat16* Bhg = g_wxt_hi + (size_t)nbase * DD;
    const __nv_bfloat16* Blg = g_wxt_lo + (size_t)nbase * DD;

    auto cp_chunk = [&](int c, int st) {
        const int k0 = c * 64;
        const uint32_t ah = sb + st * G_STAGE;
        #pragma unroll
        for (int i = 0; i < 4; i++) {
            int idx = tid + i * 256;
            int row = idx >> 3, ch = idx & 7;
            uint32_t o = (uint32_t)(row * 128) + (uint32_t)((ch * 16) ^ ((row & 7) * 16));
            CP16(ah + o,         (const char*)(Ahg + (size_t)row * DD + k0) + ch * 16);
            CP16(ah + 16384 + o, (const char*)(Alg + (size_t)row * DD + k0) + ch * 16);
            CP16(ah + 32768 + o, (const char*)(Bhg + (size_t)row * DD + k0) + ch * 16);
            CP16(ah + 49152 + o, (const char*)(Blg + (size_t)row * DD + k0) + ch * 16);
        }
        CP_COMMIT();
    };

    const int wid = tid >> 5, lane = tid & 31;
    const int wm = wid >> 2, wn = wid & 3;      // warp grid 2x4
    const int m0 = wm * 64, n0 = wn * 32;
    const int gid = lane >> 2, tig = lane & 3;

    const int a_r = lane & 15;
    const uint32_t a_k = ((lane >> 4) & 1) * 16;
    const uint32_t a_x = (uint32_t)((a_r & 7) * 16);
    const int b_r = (lane & 7) + ((lane >> 4) & 1) * 8;
    const uint32_t b_k = ((lane >> 3) & 1) * 16;
    const uint32_t b_x = (uint32_t)((lane & 7) * 16);

    float acc[4][4][4];
    #pragma unroll
    for (int mt = 0; mt < 4; mt++)
        #pragma unroll
        for (int nt = 0; nt < 4; nt++)
            #pragma unroll
            for (int q = 0; q < 4; q++) acc[mt][nt][q] = 0.0f;

    cp_chunk(0, 0);
    cp_chunk(1, 1);

    for (int c = 0; c < 16; c++) {
        if (c + 2 < 16) { cp_chunk(c + 2, (c + 2) % 3); CP_WAIT(2); }
        else if (c + 1 < 16) { CP_WAIT(1); }
        else { CP_WAIT(0); }
        __syncthreads();

        const uint32_t base = sb + (c % 3) * G_STAGE;
        #pragma unroll
        for (int kk = 0; kk < 4; kk++) {
            const uint32_t ka = ((uint32_t)(kk * 32) + a_k) ^ a_x;
            const uint32_t kb = ((uint32_t)(kk * 32) + b_k) ^ b_x;
            uint32_t ah[4][4], al[4][4], bh[2][4], bl[2][4];
            #pragma unroll
            for (int mt = 0; mt < 4; mt++) {
                uint32_t ra = base + (uint32_t)((m0 + mt * 16 + a_r) * 128);
                LDSM4(ah[mt][0], ah[mt][1], ah[mt][2], ah[mt][3], ra + ka);
                LDSM4(al[mt][0], al[mt][1], al[mt][2], al[mt][3], ra + 16384 + ka);
            }
            #pragma unroll
            for (int p = 0; p < 2; p++) {
                uint32_t rb = base + 32768 + (uint32_t)((n0 + p * 16 + b_r) * 128);
                LDSM4(bh[p][0], bh[p][1], bh[p][2], bh[p][3], rb + kb);
                LDSM4(bl[p][0], bl[p][1], bl[p][2], bl[p][3], rb + 16384 + kb);
            }
            #pragma unroll
            for (int mt = 0; mt < 4; mt++)
                #pragma unroll
                for (int nt = 0; nt < 4; nt++) {
                    const int p = nt >> 1, hf = (nt & 1) * 2;
                    MMA_BF16(acc[mt][nt][0], acc[mt][nt][1], acc[mt][nt][2], acc[mt][nt][3],
                             ah[mt][0], ah[mt][1], ah[mt][2], ah[mt][3],
                             bh[p][hf], bh[p][hf + 1]);
                    MMA_BF16(acc[mt][nt][0], acc[mt][nt][1], acc[mt][nt][2], acc[mt][nt][3],
                             ah[mt][0], ah[mt][1], ah[mt][2], ah[mt][3],
                             bl[p][hf], bl[p][hf + 1]);
                    MMA_BF16(acc[mt][nt][0], acc[mt][nt][1], acc[mt][nt][2], acc[mt][nt][3],
                             al[mt][0], al[mt][1], al[mt][2], al[mt][3],
                             bh[p][hf], bh[p][hf + 1]);
                }
        }
        __syncthreads();
    }

    #pragma unroll
    for (int nt = 0; nt < 4; nt++) {
        const int col = nbase + n0 + nt * 8 + tig * 2;
        float2 bv = *(const float2*)&g_biasp[col];
        #pragma unroll
        for (int mt = 0; mt < 4; mt++) {
            const int row = mbase + m0 + mt * 16 + gid;
            float2 v0, v1;
            v0.x = acc[mt][nt][0] + bv.x; v0.y = acc[mt][nt][1] + bv.y;
            v1.x = acc[mt][nt][2] + bv.x; v1.y = acc[mt][nt][3] + bv.y;
            *(float2*)&g_xw[(size_t)row * FOURH + col] = v0;
            *(float2*)&g_xw[(size_t)(row + 8) * FOURH + col] = v1;
        }
    }
}

// ---------------------------------------------------------------------------
// Persistent LSTM recurrence: warp-autonomous mainloop + rotated chunk order.
// 128 CTAs x 256 threads. CTA jb owns j' [jb*32, jb*32+32) (8 hidden x 4 gates).
// Warp w owns batch rows n in [w*8, w*8+8). One cheap global barrier per step
// (release-add publish, acquire poll). Chunk order rotated by jb>>3 to spread
// the 128-CTA h broadcast across all L2 slices instead of burst waves.
// ---------------------------------------------------------------------------
#define PA_HI  0                 // 64KB Wh_hi slice, 16 chunks x 4KB
#define PA_LO  65536             // 64KB Wh_lo slice
#define PB     131072            // 4 stages x 16KB (h_hi 8K | h_lo 8K)
#define PXW    196608            // 8KB xw tile (64 n x 32 j')
#define PASW   204800            // 8 warps x 1152B staging
#define P_SMEM (204800 + 9216)

__global__ __launch_bounds__(256, 1)
void lstm_persistent(float* __restrict__ out) {
    extern __shared__ char smem[];
    const uint32_t sb = smem_u32(smem);
    const int tid = threadIdx.x;
    const int jb = blockIdx.x;                 // 0..127
    const int wid = tid >> 5, lane = tid & 31;
    const int n0 = wid * 8;                    // warp's batch rows
    const int gid = lane >> 2, tig = lane & 3;
    const int rot = jb >> 3;                   // chunk-order rotation

    // A (Wh) ldmatrix addressing
    const int a_r = lane & 15;
    const uint32_t a_k = ((lane >> 4) & 1) * 16;
    const uint32_t a_x = (uint32_t)((a_r & 7) * 16);
    // B ldmatrix addressing (n8 x k32 via x4)
    const int b_row = lane & 7;
    const int b_mat = lane >> 3;

    // ---- load persistent Wh slice (16 k-chunks x 32 rows x 128B, hi+lo) ----
    {
        const __nv_bfloat16* Ahg = g_wht_hi + (size_t)jb * 32 * DD;
        const __nv_bfloat16* Alg = g_wht_lo + (size_t)jb * 32 * DD;
        #pragma unroll
        for (int i = 0; i < 16; i++) {
            int idx = tid + i * 256;
            int c = idx >> 8;
            int row = (idx >> 3) & 31;
            int ch = idx & 7;
            uint32_t o = (uint32_t)(c * 4096 + row * 128)
                       + (uint32_t)((ch * 16) ^ ((row & 7) * 16));
            CP16(sb + PA_HI + o, (const char*)(Ahg + (size_t)row * DD + c * 64) + ch * 16);
            CP16(sb + PA_LO + o, (const char*)(Alg + (size_t)row * DD + c * 64) + ch * 16);
        }
        CP_COMMIT();
        CP_WAIT(0);
        __syncthreads();
    }

    float creg[2] = {0.0f, 0.0f};

    for (unsigned t = 0; t < TT; t++) {
        const __nv_bfloat16* Bhg = g_h_hi[t & 1];
        const __nv_bfloat16* Blg = g_h_lo[t & 1];

        // warp-private B chunk load: 8 rows x 64 k (hi+lo), 4 cp/lane
        auto cp_b = [&](int c, int st) {
            const int k0 = c * 64;
            const uint32_t bb = sb + PB + (uint32_t)(st * 16384);
            #pragma unroll
            for (int q = 0; q < 2; q++) {
                int idx = lane + q * 32;      // 0..63
                int row = idx >> 3;           // 0..7
                int ch = idx & 7;
                uint32_t o = (uint32_t)((n0 + row) * 128) + (uint32_t)((ch * 16) ^ (row * 16));
                CP16(bb + o,        (const char*)(Bhg + (size_t)(n0 + row) * DD + k0) + ch * 16);
                CP16(bb + 8192 + o, (const char*)(Blg + (size_t)(n0 + row) * DD + k0) + ch * 16);
            }
        };

        // group 0: warp's xw rows + B chunk (rot)
        #pragma unroll
        for (int q = 0; q < 2; q++) {
            int idx = lane + q * 32;
            int row = idx >> 3, ch = idx & 7;
            CP16(sb + PXW + (uint32_t)((n0 + row) * 128 + ch * 16),
                 (const char*)(g_xw + ((size_t)(n0 + row) * TT + t) * FOURH + jb * 32) + ch * 16);
        }
        cp_b(rot, 0);              CP_COMMIT();
        cp_b((1 + rot) & 15, 1);   CP_COMMIT();
        cp_b((2 + rot) & 15, 2);   CP_COMMIT();

        float acc[2][4];
        #pragma unroll
        for (int mt = 0; mt < 2; mt++)
            #pragma unroll
            for (int q = 0; q < 4; q++) acc[mt][q] = 0.0f;

        for (int cc = 0; cc < 16; cc++) {
            if (cc + 3 < 16) {
                cp_b((cc + 3 + rot) & 15, (cc + 3) & 3);
                CP_COMMIT(); CP_WAIT(3);
            }
            else if (cc == 13)   { CP_WAIT(2); }
            else if (cc == 14)   { CP_WAIT(1); }
            else                 { CP_WAIT(0); }
            __syncwarp();

            const int c = (cc + rot) & 15;
            const uint32_t bst = sb + PB + (uint32_t)((cc & 3) * 16384);
            const uint32_t ahc = sb + PA_HI + (uint32_t)(c * 4096);
            const uint32_t alc = sb + PA_LO + (uint32_t)(c * 4096);
            #pragma unroll
            for (int k2 = 0; k2 < 2; k2++) {
                uint32_t bh[4], bl[4];
                const uint32_t bo = (uint32_t)((n0 + b_row) * 128)
                                  + (uint32_t)((k2 * 64 + b_mat * 16) ^ (b_row * 16));
                LDSM4(bh[0], bh[1], bh[2], bh[3], bst + bo);
                LDSM4(bl[0], bl[1], bl[2], bl[3], bst + 8192 + bo);
                #pragma unroll
                for (int hf = 0; hf < 2; hf++) {
                    const int kk = k2 * 2 + hf;
                    const uint32_t ka = ((uint32_t)(kk * 32) + a_k) ^ a_x;
                    #pragma unroll
                    for (int mt = 0; mt < 2; mt++) {
                        uint32_t ah[4], al[4];
                        const uint32_t ao = (uint32_t)((mt * 16 + a_r) * 128) + ka;
                        LDSM4(ah[0], ah[1], ah[2], ah[3], ahc + ao);
                        LDSM4(al[0], al[1], al[2], al[3], alc + ao);
                        MMA_BF16(acc[mt][0], acc[mt][1], acc[mt][2], acc[mt][3],
                                 ah[0], ah[1], ah[2], ah[3], bh[hf * 2], bh[hf * 2 + 1]);
                        MMA_BF16(acc[mt][0], acc[mt][1], acc[mt][2], acc[mt][3],
                                 ah[0], ah[1], ah[2], ah[3], bl[hf * 2], bl[hf * 2 + 1]);
                        MMA_BF16(acc[mt][0], acc[mt][1], acc[mt][2], acc[mt][3],
                                 al[0], al[1], al[2], al[3], bh[hf * 2], bh[hf * 2 + 1]);
                    }
                }
            }
        }

        // warp-local epilogue: stage acc -> asw[n_local][j'] (stride 36), gates
        float* asw = (float*)(smem + PASW + wid * 1152);
        #pragma unroll
        for (int mt = 0; mt < 2; mt++) {
            asw[(tig * 2 + 0) * 36 + mt * 16 + gid]     = acc[mt][0];
            asw[(tig * 2 + 1) * 36 + mt * 16 + gid]     = acc[mt][1];
            asw[(tig * 2 + 0) * 36 + mt * 16 + gid + 8] = acc[mt][2];
            asw[(tig * 2 + 1) * 36 + mt * 16 + gid + 8] = acc[mt][3];
        }
        __syncwarp();

        {
            const float* xws = (const float*)(smem + PXW);
            __nv_bfloat16* nhhi = g_h_hi[(t + 1) & 1];
            __nv_bfloat16* nhlo = g_h_lo[(t + 1) & 1];
            #pragma unroll
            for (int i = 0; i < 2; i++) {
                const int p = lane + i * 32;    // 0..63
                const int nl = p >> 3;          // 0..7
                const int jhl = p & 7;          // 0..7
                const float* ar = asw + nl * 36 + jhl * 4;
                const float* xr = xws + (n0 + nl) * 32 + jhl * 4;
                float ig = fsigmoid(ar[0] + xr[0]);
                float fg = fsigmoid(ar[1] + xr[1]);
                float og = fsigmoid(ar[2] + xr[2]);
                float gg = ftanh(ar[3] + xr[3]);
                float cn = fg * creg[i] + ig * gg;
                creg[i] = cn;
                float h = og * ftanh(cn);
                const int n = n0 + nl;
                const int jg = jb * 8 + jhl;
                out[((size_t)n * TT + t) * HH + jg] = h;
                __nv_bfloat16 hh = __float2bfloat16(h);
                const int hidx = n * HH + jg;
                nhhi[hidx] = hh;
                nhlo[hidx] = __float2bfloat16(h - __bfloat162float(hh));
            }
        }

        // cheap global barrier: release-add publish, acquire poll (tid 0 only)
        __syncthreads();
        if (tid == 0) {
            red_rel_add(&g_bar, 1u);
            const unsigned target = (t + 1u) * (unsigned)P_CTAS;
            while (ld_acq(&g_bar) < target) { }
        }
        __syncthreads();
    }
}

// ---------------------------------------------------------------------------
extern "C" void kernel_launch(void* const* d_in, const int* in_sizes, int n_in,
                              void* d_out, int out_size)
{
    const float* x  = (const float*)d_in[0];   // (64, 512, 1024)
    const float* h0 = (const float*)d_in[1];   // (64, 1024)
    const float* Wx = (const float*)d_in[2];   // (1024, 4096)
    const float* Wh = (const float*)d_in[3];   // (1024, 4096)
    const float* b  = (const float*)d_in[4];   // (4096,)
    float* out = (float*)d_out;                // (64, 512, 1024)

    cudaFuncSetAttribute(xw_gemm_mma,     cudaFuncAttributeMaxDynamicSharedMemorySize, G_SMEM);
    cudaFuncSetAttribute(lstm_persistent, cudaFuncAttributeMaxDynamicSharedMemorySize, P_SMEM);

    __nv_bfloat16 *wxt_hi, *wxt_lo, *wht_hi, *wht_lo;
    cudaGetSymbolAddress((void**)&wxt_hi, g_wxt_hi);
    cudaGetSymbolAddress((void**)&wxt_lo, g_wxt_lo);
    cudaGetSymbolAddress((void**)&wht_hi, g_wht_hi);
    cudaGetSymbolAddress((void**)&wht_lo, g_wht_lo);

    prep_small_kernel<<<64, 1024>>>(h0, b);
    split_x_kernel<<<(NB * TT * DD / 4) / 256, 256>>>(x);
    transpose_split_kernel<<<dim3(DD / 32, FOURH / 32), dim3(32, 8)>>>(Wx, wxt_hi, wxt_lo);
    transpose_split_kernel<<<dim3(DD / 32, FOURH / 32), dim3(32, 8)>>>(Wh, wht_hi, wht_lo);

    xw_gemm_mma<<<dim3(32, 256), 256, G_SMEM>>>();

    lstm_persistent<<<P_CTAS, 256, P_SMEM>>>(out);
}

// round 12
// speedup vs baseline: 1.2698x; 1.0003x over previous
#include <cuda_runtime.h>
#include <cuda_bf16.h>
#include <math.h>
#include <stdint.h>

#define NB 64
#define TT 512
#define DD 1024
#define HH 1024
#define FOURH 4096
#define P_CTAS 128

// ---------------------------------------------------------------------------
// Scratch (__device__ globals; allocation-free rule)
// ---------------------------------------------------------------------------
__device__ float          g_xw[(size_t)NB * TT * FOURH];      // 512 MiB xW+b (permuted cols)
__device__ __nv_bfloat16  g_xhi[(size_t)NB * TT * DD];        // 64 MiB
__device__ __nv_bfloat16  g_xlo[(size_t)NB * TT * DD];        // 64 MiB
__device__ __nv_bfloat16  g_wxt_hi[(size_t)FOURH * DD];       // WxT perm [j'][k]
__device__ __nv_bfloat16  g_wxt_lo[(size_t)FOURH * DD];
__device__ __nv_bfloat16  g_wht_hi[(size_t)FOURH * DD];       // WhT perm [j'][k]
__device__ __nv_bfloat16  g_wht_lo[(size_t)FOURH * DD];
__device__ __nv_bfloat16  g_h_hi[2][NB * HH];                 // h double buffer (bf16 hi)
__device__ __nv_bfloat16  g_h_lo[2][NB * HH];                 // h double buffer (bf16 lo)
__device__ float          g_biasp[FOURH];                     // permuted bias
__device__ unsigned       g_bar;                              // global barrier counter

// ---------------------------------------------------------------------------
// Helpers
// ---------------------------------------------------------------------------
__device__ __forceinline__ uint32_t smem_u32(const void* p) {
    uint32_t a;
    asm("{ .reg .u64 t; cvta.to.shared.u64 t, %1; cvt.u32.u64 %0, t; }"
        : "=r"(a) : "l"(p));
    return a;
}
__device__ __forceinline__ unsigned ld_acq(const unsigned* p) {
    unsigned v;
    asm volatile("ld.global.acquire.gpu.u32 %0, [%1];" : "=r"(v) : "l"(p) : "memory");
    return v;
}
__device__ __forceinline__ void red_rel_add(unsigned* p, unsigned v) {
    asm volatile("red.release.gpu.global.add.u32 [%0], %1;" :: "l"(p), "r"(v) : "memory");
}

#define CP16(dst, src) \
    asm volatile("cp.async.cg.shared.global [%0], [%1], 16;" :: "r"(dst), "l"(src) : "memory")
#define CP_COMMIT() asm volatile("cp.async.commit_group;" ::: "memory")
#define CP_WAIT(n)  asm volatile("cp.async.wait_group %0;" :: "n"(n) : "memory")

#define LDSM4(r0, r1, r2, r3, addr) \
    asm volatile("ldmatrix.sync.aligned.m8n8.x4.shared.b16 {%0,%1,%2,%3}, [%4];" \
                 : "=r"(r0), "=r"(r1), "=r"(r2), "=r"(r3) : "r"(addr))

#define MMA_BF16(c0, c1, c2, c3, a0, a1, a2, a3, b0, b1) \
    asm volatile("mma.sync.aligned.m16n8k16.row.col.f32.bf16.bf16.f32 " \
                 "{%0,%1,%2,%3}, {%4,%5,%6,%7}, {%8,%9}, {%0,%1,%2,%3};" \
                 : "+f"(c0), "+f"(c1), "+f"(c2), "+f"(c3) \
                 : "r"(a0), "r"(a1), "r"(a2), "r"(a3), "r"(b0), "r"(b1))

__device__ __forceinline__ float fsigmoid(float x) { return 1.0f / (1.0f + __expf(-x)); }
__device__ __forceinline__ float ftanh(float x)    { return 2.0f / (1.0f + __expf(-2.0f * x)) - 1.0f; }

// ---------------------------------------------------------------------------
// Prep kernels
// ---------------------------------------------------------------------------
__global__ void prep_small_kernel(const float* __restrict__ h0, const float* __restrict__ b) {
    int i = blockIdx.x * 1024 + threadIdx.x;
    if (i == 0) g_bar = 0u;
    if (i < NB * HH) {
        float v = h0[i];
        __nv_bfloat16 hi = __float2bfloat16(v);
        g_h_hi[0][i] = hi;
        g_h_lo[0][i] = __float2bfloat16(v - __bfloat162float(hi));
    }
    if (i < FOURH) {
        int jp = (i & 1023) * 4 + (i >> 10);     // perm: col g*1024+jh -> jh*4+g
        g_biasp[jp] = b[i];
    }
}

__global__ void split_x_kernel(const float* __restrict__ x) {
    size_t i = ((size_t)blockIdx.x * 256 + threadIdx.x) * 4;
    float4 v = *(const float4*)(x + i);
    __nv_bfloat16 h0 = __float2bfloat16(v.x), h1 = __float2bfloat16(v.y);
    __nv_bfloat16 h2 = __float2bfloat16(v.z), h3 = __float2bfloat16(v.w);
    __nv_bfloat162* ph = (__nv_bfloat162*)(g_xhi + i);
    __nv_bfloat162* pl = (__nv_bfloat162*)(g_xlo + i);
    ph[0] = __nv_bfloat162(h0, h1);
    ph[1] = __nv_bfloat162(h2, h3);
    pl[0] = __nv_bfloat162(__float2bfloat16(v.x - __bfloat162float(h0)),
                           __float2bfloat16(v.y - __bfloat162float(h1)));
    pl[1] = __nv_bfloat162(__float2bfloat16(v.z - __bfloat162float(h2)),
                           __float2bfloat16(v.w - __bfloat162float(h3)));
}

// W (1024 x 4096, k-major rows) -> out[j'][k] bf16 hi/lo with gate permutation.
__global__ void transpose_split_kernel(const float* __restrict__ W,
                                       __nv_bfloat16* __restrict__ ohi,
                                       __nv_bfloat16* __restrict__ olo) {
    __shared__ float ts[32][33];
    const int k0 = blockIdx.x * 32;
    const int c0 = blockIdx.y * 32;
    const int tx = threadIdx.x, ty = threadIdx.y;  // 32 x 8
    #pragma unroll
    for (int i = 0; i < 4; i++)
        ts[ty + 8 * i][tx] = W[(size_t)(k0 + ty + 8 * i) * FOURH + c0 + tx];
    __syncthreads();
    #pragma unroll
    for (int i = 0; i < 4; i++) {
        int c = c0 + ty + 8 * i;
        int jp = (c & 1023) * 4 + (c >> 10);
        float v = ts[tx][ty + 8 * i];
        __nv_bfloat16 hi = __float2bfloat16(v);
        ohi[(size_t)jp * DD + k0 + tx] = hi;
        olo[(size_t)jp * DD + k0 + tx] = __float2bfloat16(v - __bfloat162float(hi));
    }
}

// ---------------------------------------------------------------------------
// xW GEMM via mma.sync (unchanged working version)
// ---------------------------------------------------------------------------
#define G_STAGE 65536   // Ah 16K | Al 16K | Bh 16K | Bl 16K
#define G_SMEM  (3 * G_STAGE)

__global__ __launch_bounds__(256, 1)
void xw_gemm_mma() {
    extern __shared__ char smem[];
    const uint32_t sb = smem_u32(smem);
    const int tid = threadIdx.x;
    const int nbase = blockIdx.x * 128;
    const int mbase = blockIdx.y * 128;

    const __nv_bfloat16* Ahg = g_xhi + (size_t)mbase * DD;
    const __nv_bfloat16* Alg = g_xlo + (size_t)mbase * DD;
    const __nv_bfloat16* Bhg = g_wxt_hi + (size_t)nbase * DD;
    const __nv_bfloat16* Blg = g_wxt_lo + (size_t)nbase * DD;

    auto cp_chunk = [&](int c, int st) {
        const int k0 = c * 64;
        const uint32_t ah = sb + st * G_STAGE;
        #pragma unroll
        for (int i = 0; i < 4; i++) {
            int idx = tid + i * 256;
            int row = idx >> 3, ch = idx & 7;
            uint32_t o = (uint32_t)(row * 128) + (uint32_t)((ch * 16) ^ ((row & 7) * 16));
            CP16(ah + o,         (const char*)(Ahg + (size_t)row * DD + k0) + ch * 16);
            CP16(ah + 16384 + o, (const char*)(Alg + (size_t)row * DD + k0) + ch * 16);
            CP16(ah + 32768 + o, (const char*)(Bhg + (size_t)row * DD + k0) + ch * 16);
            CP16(ah + 49152 + o, (const char*)(Blg + (size_t)row * DD + k0) + ch * 16);
        }
        CP_COMMIT();
    };

    const int wid = tid >> 5, lane = tid & 31;
    const int wm = wid >> 2, wn = wid & 3;      // warp grid 2x4
    const int m0 = wm * 64, n0 = wn * 32;
    const int gid = lane >> 2, tig = lane & 3;

    const int a_r = lane & 15;
    const uint32_t a_k = ((lane >> 4) & 1) * 16;
    const uint32_t a_x = (uint32_t)((a_r & 7) * 16);
    const int b_r = (lane & 7) + ((lane >> 4) & 1) * 8;
    const uint32_t b_k = ((lane >> 3) & 1) * 16;
    const uint32_t b_x = (uint32_t)((lane & 7) * 16);

    float acc[4][4][4];
    #pragma unroll
    for (int mt = 0; mt < 4; mt++)
        #pragma unroll
        for (int nt = 0; nt < 4; nt++)
            #pragma unroll
            for (int q = 0; q < 4; q++) acc[mt][nt][q] = 0.0f;

    cp_chunk(0, 0);
    cp_chunk(1, 1);

    for (int c = 0; c < 16; c++) {
        if (c + 2 < 16) { cp_chunk(c + 2, (c + 2) % 3); CP_WAIT(2); }
        else if (c + 1 < 16) { CP_WAIT(1); }
        else { CP_WAIT(0); }
        __syncthreads();

        const uint32_t base = sb + (c % 3) * G_STAGE;
        #pragma unroll
        for (int kk = 0; kk < 4; kk++) {
            const uint32_t ka = ((uint32_t)(kk * 32) + a_k) ^ a_x;
            const uint32_t kb = ((uint32_t)(kk * 32) + b_k) ^ b_x;
            uint32_t ah[4][4], al[4][4], bh[2][4], bl[2][4];
            #pragma unroll
            for (int mt = 0; mt < 4; mt++) {
                uint32_t ra = base + (uint32_t)((m0 + mt * 16 + a_r) * 128);
                LDSM4(ah[mt][0], ah[mt][1], ah[mt][2], ah[mt][3], ra + ka);
                LDSM4(al[mt][0], al[mt][1], al[mt][2], al[mt][3], ra + 16384 + ka);
            }
            #pragma unroll
            for (int p = 0; p < 2; p++) {
                uint32_t rb = base + 32768 + (uint32_t)((n0 + p * 16 + b_r) * 128);
                LDSM4(bh[p][0], bh[p][1], bh[p][2], bh[p][3], rb + kb);
                LDSM4(bl[p][0], bl[p][1], bl[p][2], bl[p][3], rb + 16384 + kb);
            }
            #pragma unroll
            for (int mt = 0; mt < 4; mt++)
                #pragma unroll
                for (int nt = 0; nt < 4; nt++) {
                    const int p = nt >> 1, hf = (nt & 1) * 2;
                    MMA_BF16(acc[mt][nt][0], acc[mt][nt][1], acc[mt][nt][2], acc[mt][nt][3],
                             ah[mt][0], ah[mt][1], ah[mt][2], ah[mt][3],
                             bh[p][hf], bh[p][hf + 1]);
                    MMA_BF16(acc[mt][nt][0], acc[mt][nt][1], acc[mt][nt][2], acc[mt][nt][3],
                             ah[mt][0], ah[mt][1], ah[mt][2], ah[mt][3],
                             bl[p][hf], bl[p][hf + 1]);
                    MMA_BF16(acc[mt][nt][0], acc[mt][nt][1], acc[mt][nt][2], acc[mt][nt][3],
                             al[mt][0], al[mt][1], al[mt][2], al[mt][3],
                             bh[p][hf], bh[p][hf + 1]);
                }
        }
        __syncthreads();
    }

    #pragma unroll
    for (int nt = 0; nt < 4; nt++) {
        const int col = nbase + n0 + nt * 8 + tig * 2;
        float2 bv = *(const float2*)&g_biasp[col];
        #pragma unroll
        for (int mt = 0; mt < 4; mt++) {
            const int row = mbase + m0 + mt * 16 + gid;
            float2 v0, v1;
            v0.x = acc[mt][nt][0] + bv.x; v0.y = acc[mt][nt][1] + bv.y;
            v1.x = acc[mt][nt][2] + bv.x; v1.y = acc[mt][nt][3] + bv.y;
            *(float2*)&g_xw[(size_t)row * FOURH + col] = v0;
            *(float2*)&g_xw[(size_t)(row + 8) * FOURH + col] = v1;
        }
    }
}

// ---------------------------------------------------------------------------
// Persistent LSTM recurrence: warp-autonomous mainloop + rotated chunk order.
// 128 CTAs x 256 threads. CTA jb owns j' [jb*32, jb*32+32) (8 hidden x 4 gates).
// Warp w owns batch rows n in [w*8, w*8+8). One cheap global barrier per step
// (release-add publish, acquire poll). Chunk order rotated by jb>>3 to spread
// the 128-CTA h broadcast across all L2 slices instead of burst waves.
// ---------------------------------------------------------------------------
#define PA_HI  0                 // 64KB Wh_hi slice, 16 chunks x 4KB
#define PA_LO  65536             // 64KB Wh_lo slice
#define PB     131072            // 4 stages x 16KB (h_hi 8K | h_lo 8K)
#define PXW    196608            // 8KB xw tile (64 n x 32 j')
#define PASW   204800            // 8 warps x 1152B staging
#define P_SMEM (204800 + 9216)

__global__ __launch_bounds__(256, 1)
void lstm_persistent(float* __restrict__ out) {
    extern __shared__ char smem[];
    const uint32_t sb = smem_u32(smem);
    const int tid = threadIdx.x;
    const int jb = blockIdx.x;                 // 0..127
    const int wid = tid >> 5, lane = tid & 31;
    const int n0 = wid * 8;                    // warp's batch rows
    const int gid = lane >> 2, tig = lane & 3;
    const int rot = jb >> 3;                   // chunk-order rotation

    // A (Wh) ldmatrix addressing
    const int a_r = lane & 15;
    const uint32_t a_k = ((lane >> 4) & 1) * 16;
    const uint32_t a_x = (uint32_t)((a_r & 7) * 16);
    // B ldmatrix addressing (n8 x k32 via x4)
    const int b_row = lane & 7;
    const int b_mat = lane >> 3;

    // ---- load persistent Wh slice (16 k-chunks x 32 rows x 128B, hi+lo) ----
    {
        const __nv_bfloat16* Ahg = g_wht_hi + (size_t)jb * 32 * DD;
        const __nv_bfloat16* Alg = g_wht_lo + (size_t)jb * 32 * DD;
        #pragma unroll
        for (int i = 0; i < 16; i++) {
            int idx = tid + i * 256;
            int c = idx >> 8;
            int row = (idx >> 3) & 31;
            int ch = idx & 7;
            uint32_t o = (uint32_t)(c * 4096 + row * 128)
                       + (uint32_t)((ch * 16) ^ ((row & 7) * 16));
            CP16(sb + PA_HI + o, (const char*)(Ahg + (size_t)row * DD + c * 64) + ch * 16);
            CP16(sb + PA_LO + o, (const char*)(Alg + (size_t)row * DD + c * 64) + ch * 16);
        }
        CP_COMMIT();
        CP_WAIT(0);
        __syncthreads();
    }

    float creg[2] = {0.0f, 0.0f};

    for (unsigned t = 0; t < TT; t++) {
        const __nv_bfloat16* Bhg = g_h_hi[t & 1];
        const __nv_bfloat16* Blg = g_h_lo[t & 1];

        // warp-private B chunk load: 8 rows x 64 k (hi+lo), 4 cp/lane
        auto cp_b = [&](int c, int st) {
            const int k0 = c * 64;
            const uint32_t bb = sb + PB + (uint32_t)(st * 16384);
            #pragma unroll
            for (int q = 0; q < 2; q++) {
                int idx = lane + q * 32;      // 0..63
                int row = idx >> 3;           // 0..7
                int ch = idx & 7;
                uint32_t o = (uint32_t)((n0 + row) * 128) + (uint32_t)((ch * 16) ^ (row * 16));
                CP16(bb + o,        (const char*)(Bhg + (size_t)(n0 + row) * DD + k0) + ch * 16);
                CP16(bb + 8192 + o, (const char*)(Blg + (size_t)(n0 + row) * DD + k0) + ch * 16);
            }
        };

        // group 0: warp's xw rows + B chunk (rot)
        #pragma unroll
        for (int q = 0; q < 2; q++) {
            int idx = lane + q * 32;
            int row = idx >> 3, ch = idx & 7;
            CP16(sb + PXW + (uint32_t)((n0 + row) * 128 + ch * 16),
                 (const char*)(g_xw + ((size_t)(n0 + row) * TT + t) * FOURH + jb * 32) + ch * 16);
        }
        cp_b(rot, 0);              CP_COMMIT();
        cp_b((1 + rot) & 15, 1);   CP_COMMIT();
        cp_b((2 + rot) & 15, 2);   CP_COMMIT();

        float acc[2][4];
        #pragma unroll
        for (int mt = 0; mt < 2; mt++)
            #pragma unroll
            for (int q = 0; q < 4; q++) acc[mt][q] = 0.0f;

        for (int cc = 0; cc < 16; cc++) {
            if (cc + 3 < 16) {
                cp_b((cc + 3 + rot) & 15, (cc + 3) & 3);
                CP_COMMIT(); CP_WAIT(3);
            }
            else if (cc == 13)   { CP_WAIT(2); }
            else if (cc == 14)   { CP_WAIT(1); }
            else                 { CP_WAIT(0); }
            __syncwarp();

            const int c = (cc + rot) & 15;
            const uint32_t bst = sb + PB + (uint32_t)((cc & 3) * 16384);
            const uint32_t ahc = sb + PA_HI + (uint32_t)(c * 4096);
            const uint32_t alc = sb + PA_LO + (uint32_t)(c * 4096);
            #pragma unroll
            for (int k2 = 0; k2 < 2; k2++) {
                uint32_t bh[4], bl[4];
                const uint32_t bo = (uint32_t)((n0 + b_row) * 128)
                                  + (uint32_t)((k2 * 64 + b_mat * 16) ^ (b_row * 16));
                LDSM4(bh[0], bh[1], bh[2], bh[3], bst + bo);
                LDSM4(bl[0], bl[1], bl[2], bl[3], bst + 8192 + bo);
                #pragma unroll
                for (int hf = 0; hf < 2; hf++) {
                    const int kk = k2 * 2 + hf;
                    const uint32_t ka = ((uint32_t)(kk * 32) + a_k) ^ a_x;
                    #pragma unroll
                    for (int mt = 0; mt < 2; mt++) {
                        uint32_t ah[4], al[4];
                        const uint32_t ao = (uint32_t)((mt * 16 + a_r) * 128) + ka;
                        LDSM4(ah[0], ah[1], ah[2], ah[3], ahc + ao);
                        LDSM4(al[0], al[1], al[2], al[3], alc + ao);
                        MMA_BF16(acc[mt][0], acc[mt][1], acc[mt][2], acc[mt][3],
                                 ah[0], ah[1], ah[2], ah[3], bh[hf * 2], bh[hf * 2 + 1]);
                        MMA_BF16(acc[mt][0], acc[mt][1], acc[mt][2], acc[mt][3],
                                 ah[0], ah[1], ah[2], ah[3], bl[hf * 2], bl[hf * 2 + 1]);
                        MMA_BF16(acc[mt][0], acc[mt][1], acc[mt][2], acc[mt][3],
                                 al[0], al[1], al[2], al[3], bh[hf * 2], bh[hf * 2 + 1]);
                    }
                }
            }
        }

        // warp-local epilogue: stage acc -> asw[n_local][j'] (stride 36), gates
        float* asw = (float*)(smem + PASW + wid * 1152);
        #pragma unroll
        for (int mt = 0; mt < 2; mt++) {
            asw[(tig * 2 + 0) * 36 + mt * 16 + gid]     = acc[mt][0];
            asw[(tig * 2 + 1) * 36 + mt * 16 + gid]     = acc[mt][1];
            asw[(tig * 2 + 0) * 36 + mt * 16 + gid + 8] = acc[mt][2];
            asw[(tig * 2 + 1) * 36 + mt * 16 + gid + 8] = acc[mt][3];
        }
        __syncwarp();

        {
            const float* xws = (const float*)(smem + PXW);
            __nv_bfloat16* nhhi = g_h_hi[(t + 1) & 1];
            __nv_bfloat16* nhlo = g_h_lo[(t + 1) & 1];
            #pragma unroll
            for (int i = 0; i < 2; i++) {
                const int p = lane + i * 32;    // 0..63
                const int nl = p >> 3;          // 0..7
                const int jhl = p & 7;          // 0..7
                const float* ar = asw + nl * 36 + jhl * 4;
                const float* xr = xws + (n0 + nl) * 32 + jhl * 4;
                float ig = fsigmoid(ar[0] + xr[0]);
                float fg = fsigmoid(ar[1] + xr[1]);
                float og = fsigmoid(ar[2] + xr[2]);
                float gg = ftanh(ar[3] + xr[3]);
                float cn = fg * creg[i] + ig * gg;
                creg[i] = cn;
                float h = og * ftanh(cn);
                const int n = n0 + nl;
                const int jg = jb * 8 + jhl;
                out[((size_t)n * TT + t) * HH + jg] = h;
                __nv_bfloat16 hh = __float2bfloat16(h);
                const int hidx = n * HH + jg;
                nhhi[hidx] = hh;
                nhlo[hidx] = __float2bfloat16(h - __bfloat162float(hh));
            }
        }

        // cheap global barrier: release-add publish, acquire poll (tid 0 only)
        __syncthreads();
        if (tid == 0) {
            red_rel_add(&g_bar, 1u);
            const unsigned target = (t + 1u) * (unsigned)P_CTAS;
            while (ld_acq(&g_bar) < target) { }
        }
        __syncthreads();
    }
}

// ---------------------------------------------------------------------------
extern "C" void kernel_launch(void* const* d_in, const int* in_sizes, int n_in,
                              void* d_out, int out_size)
{
    const float* x  = (const float*)d_in[0];   // (64, 512, 1024)
    const float* h0 = (const float*)d_in[1];   // (64, 1024)
    const float* Wx = (const float*)d_in[2];   // (1024, 4096)
    const float* Wh = (const float*)d_in[3];   // (1024, 4096)
    const float* b  = (const float*)d_in[4];   // (4096,)
    float* out = (float*)d_out;                // (64, 512, 1024)

    cudaFuncSetAttribute(xw_gemm_mma,     cudaFuncAttributeMaxDynamicSharedMemorySize, G_SMEM);
    cudaFuncSetAttribute(lstm_persistent, cudaFuncAttributeMaxDynamicSharedMemorySize, P_SMEM);

    __nv_bfloat16 *wxt_hi, *wxt_lo, *wht_hi, *wht_lo;
    cudaGetSymbolAddress((void**)&wxt_hi, g_wxt_hi);
    cudaGetSymbolAddress((void**)&wxt_lo, g_wxt_lo);
    cudaGetSymbolAddress((void**)&wht_hi, g_wht_hi);
    cudaGetSymbolAddress((void**)&wht_lo, g_wht_lo);

    prep_small_kernel<<<64, 1024>>>(h0, b);
    split_x_kernel<<<(NB * TT * DD / 4) / 256, 256>>>(x);
    transpose_split_kernel<<<dim3(DD / 32, FOURH / 32), dim3(32, 8)>>>(Wx, wxt_hi, wxt_lo);
    transpose_split_kernel<<<dim3(DD / 32, FOURH / 32), dim3(32, 8)>>>(Wh, wht_hi, wht_lo);

    xw_gemm_mma<<<dim3(32, 256), 256, G_SMEM>>>();

    lstm_persistent<<<P_CTAS, 256, P_SMEM>>>(out);
}

// round 13
// speedup vs baseline: 1.4683x; 1.1563x over previous
#include <cuda_runtime.h>
#include <cuda_fp16.h>
#include <math.h>
#include <stdint.h>

#define NB 64
#define TT 512
#define DD 1024
#define HH 1024
#define FOURH 4096
#define P_CTAS 128

// ---------------------------------------------------------------------------
// Scratch (__device__ globals; allocation-free rule)
// ---------------------------------------------------------------------------
__device__ float    g_xw[(size_t)NB * TT * FOURH];      // 512 MiB xW+b (permuted cols)
__device__ __half   g_xh[(size_t)NB * TT * DD];         // 64 MiB x fp16
__device__ __half   g_wxt_hi[(size_t)FOURH * DD];       // WxT perm [j'][k] fp16 hi
__device__ __half   g_wxt_lo[(size_t)FOURH * DD];       // fp16 lo
__device__ __half   g_wht_hi[(size_t)FOURH * DD];       // WhT perm [j'][k] fp16 hi
__device__ __half   g_wht_lo[(size_t)FOURH * DD];       // fp16 lo
__device__ __half   g_h[2][NB * HH];                    // h double buffer (fp16)
__device__ float    g_biasp[FOURH];                     // permuted bias
__device__ unsigned g_bar;                              // global barrier counter

// ---------------------------------------------------------------------------
// Helpers
// ---------------------------------------------------------------------------
__device__ __forceinline__ uint32_t smem_u32(const void* p) {
    uint32_t a;
    asm("{ .reg .u64 t; cvta.to.shared.u64 t, %1; cvt.u32.u64 %0, t; }"
        : "=r"(a) : "l"(p));
    return a;
}
__device__ __forceinline__ unsigned ld_acq(const unsigned* p) {
    unsigned v;
    asm volatile("ld.global.acquire.gpu.u32 %0, [%1];" : "=r"(v) : "l"(p) : "memory");
    return v;
}
__device__ __forceinline__ void red_rel_add(unsigned* p, unsigned v) {
    asm volatile("red.release.gpu.global.add.u32 [%0], %1;" :: "l"(p), "r"(v) : "memory");
}

#define CP16(dst, src) \
    asm volatile("cp.async.cg.shared.global [%0], [%1], 16;" :: "r"(dst), "l"(src) : "memory")
#define CP_COMMIT() asm volatile("cp.async.commit_group;" ::: "memory")
#define CP_WAIT(n)  asm volatile("cp.async.wait_group %0;" :: "n"(n) : "memory")

#define LDSM4(r0, r1, r2, r3, addr) \
    asm volatile("ldmatrix.sync.aligned.m8n8.x4.shared.b16 {%0,%1,%2,%3}, [%4];" \
                 : "=r"(r0), "=r"(r1), "=r"(r2), "=r"(r3) : "r"(addr))

#define MMA_F16(c0, c1, c2, c3, a0, a1, a2, a3, b0, b1) \
    asm volatile("mma.sync.aligned.m16n8k16.row.col.f32.f16.f16.f32 " \
                 "{%0,%1,%2,%3}, {%4,%5,%6,%7}, {%8,%9}, {%0,%1,%2,%3};" \
                 : "+f"(c0), "+f"(c1), "+f"(c2), "+f"(c3) \
                 : "r"(a0), "r"(a1), "r"(a2), "r"(a3), "r"(b0), "r"(b1))

__device__ __forceinline__ float fsigmoid(float x) { return 1.0f / (1.0f + __expf(-x)); }
__device__ __forceinline__ float ftanh(float x)    { return 2.0f / (1.0f + __expf(-2.0f * x)) - 1.0f; }

// ---------------------------------------------------------------------------
// Prep kernels
// ---------------------------------------------------------------------------
__global__ void prep_small_kernel(const float* __restrict__ h0, const float* __restrict__ b) {
    int i = blockIdx.x * 1024 + threadIdx.x;
    if (i == 0) g_bar = 0u;
    if (i < NB * HH) {
        g_h[0][i] = __float2half_rn(h0[i]);
    }
    if (i < FOURH) {
        int jp = (i & 1023) * 4 + (i >> 10);     // perm: col g*1024+jh -> jh*4+g
        g_biasp[jp] = b[i];
    }
}

__global__ void split_x_kernel(const float* __restrict__ x) {
    size_t i = ((size_t)blockIdx.x * 256 + threadIdx.x) * 4;
    float4 v = *(const float4*)(x + i);
    __half2* ph = (__half2*)(g_xh + i);
    ph[0] = __floats2half2_rn(v.x, v.y);
    ph[1] = __floats2half2_rn(v.z, v.w);
}

// W (1024 x 4096, k-major rows) -> out[j'][k] fp16 hi/lo with gate permutation.
__global__ void transpose_split_kernel(const float* __restrict__ W,
                                       __half* __restrict__ ohi,
                                       __half* __restrict__ olo) {
    __shared__ float ts[32][33];
    const int k0 = blockIdx.x * 32;
    const int c0 = blockIdx.y * 32;
    const int tx = threadIdx.x, ty = threadIdx.y;  // 32 x 8
    #pragma unroll
    for (int i = 0; i < 4; i++)
        ts[ty + 8 * i][tx] = W[(size_t)(k0 + ty + 8 * i) * FOURH + c0 + tx];
    __syncthreads();
    #pragma unroll
    for (int i = 0; i < 4; i++) {
        int c = c0 + ty + 8 * i;
        int jp = (c & 1023) * 4 + (c >> 10);
        float v = ts[tx][ty + 8 * i];
        __half hi = __float2half_rn(v);
        ohi[(size_t)jp * DD + k0 + tx] = hi;
        olo[(size_t)jp * DD + k0 + tx] = __float2half_rn(v - __half2float(hi));
    }
}

// ---------------------------------------------------------------------------
// xW GEMM via mma.sync, fp16 2-term: g_xw[token][j'] = x @ (WxT_hi+WxT_lo)^T + b
// CTA tile 128(token) x 128(j'), k-chunk 64, 3-stage cp.async pipeline.
// ---------------------------------------------------------------------------
#define G_STAGE 49152   // A 16K | Bh 16K | Bl 16K
#define G_SMEM  (3 * G_STAGE)

__global__ __launch_bounds__(256, 1)
void xw_gemm_mma() {
    extern __shared__ char smem[];
    const uint32_t sb = smem_u32(smem);
    const int tid = threadIdx.x;
    const int nbase = blockIdx.x * 128;
    const int mbase = blockIdx.y * 128;

    const __half* Ag  = g_xh + (size_t)mbase * DD;
    const __half* Bhg = g_wxt_hi + (size_t)nbase * DD;
    const __half* Blg = g_wxt_lo + (size_t)nbase * DD;

    auto cp_chunk = [&](int c, int st) {
        const int k0 = c * 64;
        const uint32_t ah = sb + st * G_STAGE;
        #pragma unroll
        for (int i = 0; i < 4; i++) {
            int idx = tid + i * 256;
            int row = idx >> 3, ch = idx & 7;
            uint32_t o = (uint32_t)(row * 128) + (uint32_t)((ch * 16) ^ ((row & 7) * 16));
            CP16(ah + o,         (const char*)(Ag  + (size_t)row * DD + k0) + ch * 16);
            CP16(ah + 16384 + o, (const char*)(Bhg + (size_t)row * DD + k0) + ch * 16);
            CP16(ah + 32768 + o, (const char*)(Blg + (size_t)row * DD + k0) + ch * 16);
        }
        CP_COMMIT();
    };

    const int wid = tid >> 5, lane = tid & 31;
    const int wm = wid >> 2, wn = wid & 3;      // warp grid 2x4
    const int m0 = wm * 64, n0 = wn * 32;
    const int gid = lane >> 2, tig = lane & 3;

    const int a_r = lane & 15;
    const uint32_t a_k = ((lane >> 4) & 1) * 16;
    const uint32_t a_x = (uint32_t)((a_r & 7) * 16);
    const int b_r = (lane & 7) + ((lane >> 4) & 1) * 8;
    const uint32_t b_k = ((lane >> 3) & 1) * 16;
    const uint32_t b_x = (uint32_t)((lane & 7) * 16);

    float acc[4][4][4];
    #pragma unroll
    for (int mt = 0; mt < 4; mt++)
        #pragma unroll
        for (int nt = 0; nt < 4; nt++)
            #pragma unroll
            for (int q = 0; q < 4; q++) acc[mt][nt][q] = 0.0f;

    cp_chunk(0, 0);
    cp_chunk(1, 1);

    for (int c = 0; c < 16; c++) {
        if (c + 2 < 16) { cp_chunk(c + 2, (c + 2) % 3); CP_WAIT(2); }
        else if (c + 1 < 16) { CP_WAIT(1); }
        else { CP_WAIT(0); }
        __syncthreads();

        const uint32_t base = sb + (c % 3) * G_STAGE;
        #pragma unroll
        for (int kk = 0; kk < 4; kk++) {
            const uint32_t ka = ((uint32_t)(kk * 32) + a_k) ^ a_x;
            const uint32_t kb = ((uint32_t)(kk * 32) + b_k) ^ b_x;
            uint32_t a[4][4], bh[2][4], bl[2][4];
            #pragma unroll
            for (int mt = 0; mt < 4; mt++) {
                uint32_t ra = base + (uint32_t)((m0 + mt * 16 + a_r) * 128);
                LDSM4(a[mt][0], a[mt][1], a[mt][2], a[mt][3], ra + ka);
            }
            #pragma unroll
            for (int p = 0; p < 2; p++) {
                uint32_t rb = base + 16384 + (uint32_t)((n0 + p * 16 + b_r) * 128);
                LDSM4(bh[p][0], bh[p][1], bh[p][2], bh[p][3], rb + kb);
                LDSM4(bl[p][0], bl[p][1], bl[p][2], bl[p][3], rb + 16384 + kb);
            }
            #pragma unroll
            for (int mt = 0; mt < 4; mt++)
                #pragma unroll
                for (int nt = 0; nt < 4; nt++) {
                    const int p = nt >> 1, hf = (nt & 1) * 2;
                    MMA_F16(acc[mt][nt][0], acc[mt][nt][1], acc[mt][nt][2], acc[mt][nt][3],
                            a[mt][0], a[mt][1], a[mt][2], a[mt][3],
                            bh[p][hf], bh[p][hf + 1]);
                    MMA_F16(acc[mt][nt][0], acc[mt][nt][1], acc[mt][nt][2], acc[mt][nt][3],
                            a[mt][0], a[mt][1], a[mt][2], a[mt][3],
                            bl[p][hf], bl[p][hf + 1]);
                }
        }
        __syncthreads();
    }

    #pragma unroll
    for (int nt = 0; nt < 4; nt++) {
        const int col = nbase + n0 + nt * 8 + tig * 2;
        float2 bv = *(const float2*)&g_biasp[col];
        #pragma unroll
        for (int mt = 0; mt < 4; mt++) {
            const int row = mbase + m0 + mt * 16 + gid;
            float2 v0, v1;
            v0.x = acc[mt][nt][0] + bv.x; v0.y = acc[mt][nt][1] + bv.y;
            v1.x = acc[mt][nt][2] + bv.x; v1.y = acc[mt][nt][3] + bv.y;
            *(float2*)&g_xw[(size_t)row * FOURH + col] = v0;
            *(float2*)&g_xw[(size_t)(row + 8) * FOURH + col] = v1;
        }
    }
}

// ---------------------------------------------------------------------------
// Persistent LSTM recurrence, fp16 2-term: D = (Wh_hi + Wh_lo) . h^T.
// 128 CTAs x 256 threads. CTA jb owns j' [jb*32, jb*32+32). Warp w owns batch
// rows [w*8, w*8+8). Wh hi/lo resident in SMEM; h single fp16 streamed.
// One cheap global barrier per step; chunk order rotated by jb>>3.
// ---------------------------------------------------------------------------
#define PA_HI  0                 // 64KB Wh_hi slice, 16 chunks x 4KB
#define PA_LO  65536             // 64KB Wh_lo slice
#define PB     131072            // 4 stages x 8KB (h fp16)
#define PXW    163840            // 8KB xw tile (64 n x 32 j')
#define PASW   172032            // 8 warps x 1152B staging
#define P_SMEM (172032 + 9216)

__global__ __launch_bounds__(256, 1)
void lstm_persistent(float* __restrict__ out) {
    extern __shared__ char smem[];
    const uint32_t sb = smem_u32(smem);
    const int tid = threadIdx.x;
    const int jb = blockIdx.x;                 // 0..127
    const int wid = tid >> 5, lane = tid & 31;
    const int n0 = wid * 8;                    // warp's batch rows
    const int gid = lane >> 2, tig = lane & 3;
    const int rot = jb >> 3;                   // chunk-order rotation

    // A (Wh) ldmatrix addressing
    const int a_r = lane & 15;
    const uint32_t a_k = ((lane >> 4) & 1) * 16;
    const uint32_t a_x = (uint32_t)((a_r & 7) * 16);
    // B ldmatrix addressing (n8 x k32 via x4)
    const int b_row = lane & 7;
    const int b_mat = lane >> 3;

    // ---- load persistent Wh slice (16 k-chunks x 32 rows x 128B, hi+lo) ----
    {
        const __half* Ahg = g_wht_hi + (size_t)jb * 32 * DD;
        const __half* Alg = g_wht_lo + (size_t)jb * 32 * DD;
        #pragma unroll
        for (int i = 0; i < 16; i++) {
            int idx = tid + i * 256;
            int c = idx >> 8;
            int row = (idx >> 3) & 31;
            int ch = idx & 7;
            uint32_t o = (uint32_t)(c * 4096 + row * 128)
                       + (uint32_t)((ch * 16) ^ ((row & 7) * 16));
            CP16(sb + PA_HI + o, (const char*)(Ahg + (size_t)row * DD + c * 64) + ch * 16);
            CP16(sb + PA_LO + o, (const char*)(Alg + (size_t)row * DD + c * 64) + ch * 16);
        }
        CP_COMMIT();
        CP_WAIT(0);
        __syncthreads();
    }

    float creg[2] = {0.0f, 0.0f};

    for (unsigned t = 0; t < TT; t++) {
        const __half* Bg = g_h[t & 1];

        // warp-private B chunk load: 8 rows x 64 k fp16, 2 cp/lane
        auto cp_b = [&](int c, int st) {
            const int k0 = c * 64;
            const uint32_t bb = sb + PB + (uint32_t)(st * 8192);
            #pragma unroll
            for (int q = 0; q < 2; q++) {
                int idx = lane + q * 32;      // 0..63
                int row = idx >> 3;           // 0..7
                int ch = idx & 7;
                uint32_t o = (uint32_t)((n0 + row) * 128) + (uint32_t)((ch * 16) ^ (row * 16));
                CP16(bb + o, (const char*)(Bg + (size_t)(n0 + row) * DD + k0) + ch * 16);
            }
        };

        // group 0: warp's xw rows + B chunk (rot)
        #pragma unroll
        for (int q = 0; q < 2; q++) {
            int idx = lane + q * 32;
            int row = idx >> 3, ch = idx & 7;
            CP16(sb + PXW + (uint32_t)((n0 + row) * 128 + ch * 16),
                 (const char*)(g_xw + ((size_t)(n0 + row) * TT + t) * FOURH + jb * 32) + ch * 16);
        }
        cp_b(rot, 0);              CP_COMMIT();
        cp_b((1 + rot) & 15, 1);   CP_COMMIT();
        cp_b((2 + rot) & 15, 2);   CP_COMMIT();

        float acc[2][4];
        #pragma unroll
        for (int mt = 0; mt < 2; mt++)
            #pragma unroll
            for (int q = 0; q < 4; q++) acc[mt][q] = 0.0f;

        for (int cc = 0; cc < 16; cc++) {
            if (cc + 3 < 16) {
                cp_b((cc + 3 + rot) & 15, (cc + 3) & 3);
                CP_COMMIT(); CP_WAIT(3);
            }
            else if (cc == 13)   { CP_WAIT(2); }
            else if (cc == 14)   { CP_WAIT(1); }
            else                 { CP_WAIT(0); }
            __syncwarp();

            const int c = (cc + rot) & 15;
            const uint32_t bst = sb + PB + (uint32_t)((cc & 3) * 8192);
            const uint32_t ahc = sb + PA_HI + (uint32_t)(c * 4096);
            const uint32_t alc = sb + PA_LO + (uint32_t)(c * 4096);
            #pragma unroll
            for (int k2 = 0; k2 < 2; k2++) {
                uint32_t bh[4];
                const uint32_t bo = (uint32_t)((n0 + b_row) * 128)
                                  + (uint32_t)((k2 * 64 + b_mat * 16) ^ (b_row * 16));
                LDSM4(bh[0], bh[1], bh[2], bh[3], bst + bo);
                #pragma unroll
                for (int hf = 0; hf < 2; hf++) {
                    const int kk = k2 * 2 + hf;
                    const uint32_t ka = ((uint32_t)(kk * 32) + a_k) ^ a_x;
                    #pragma unroll
                    for (int mt = 0; mt < 2; mt++) {
                        uint32_t ah[4], al[4];
                        const uint32_t ao = (uint32_t)((mt * 16 + a_r) * 128) + ka;
                        LDSM4(ah[0], ah[1], ah[2], ah[3], ahc + ao);
                        LDSM4(al[0], al[1], al[2], al[3], alc + ao);
                        MMA_F16(acc[mt][0], acc[mt][1], acc[mt][2], acc[mt][3],
                                ah[0], ah[1], ah[2], ah[3], bh[hf * 2], bh[hf * 2 + 1]);
                        MMA_F16(acc[mt][0], acc[mt][1], acc[mt][2], acc[mt][3],
                                al[0], al[1], al[2], al[3], bh[hf * 2], bh[hf * 2 + 1]);
                    }
                }
            }
        }

        // warp-local epilogue: stage acc -> asw[n_local][j'] (stride 36), gates
        float* asw = (float*)(smem + PASW + wid * 1152);
        #pragma unroll
        for (int mt = 0; mt < 2; mt++) {
            asw[(tig * 2 + 0) * 36 + mt * 16 + gid]     = acc[mt][0];
            asw[(tig * 2 + 1) * 36 + mt * 16 + gid]     = acc[mt][1];
            asw[(tig * 2 + 0) * 36 + mt * 16 + gid + 8] = acc[mt][2];
            asw[(tig * 2 + 1) * 36 + mt * 16 + gid + 8] = acc[mt][3];
        }
        __syncwarp();

        {
            const float* xws = (const float*)(smem + PXW);
            __half* nh = g_h[(t + 1) & 1];
            #pragma unroll
            for (int i = 0; i < 2; i++) {
                const int p = lane + i * 32;    // 0..63
                const int nl = p >> 3;          // 0..7
                const int jhl = p & 7;          // 0..7
                const float* ar = asw + nl * 36 + jhl * 4;
                const float* xr = xws + (n0 + nl) * 32 + jhl * 4;
                float ig = fsigmoid(ar[0] + xr[0]);
                float fg = fsigmoid(ar[1] + xr[1]);
                float og = fsigmoid(ar[2] + xr[2]);
                float gg = ftanh(ar[3] + xr[3]);
                float cn = fg * creg[i] + ig * gg;
                creg[i] = cn;
                float h = og * ftanh(cn);
                const int n = n0 + nl;
                const int jg = jb * 8 + jhl;
                out[((size_t)n * TT + t) * HH + jg] = h;
                nh[n * HH + jg] = __float2half_rn(h);
            }
        }

        // cheap global barrier: release-add publish, acquire poll (tid 0 only)
        __syncthreads();
        if (tid == 0) {
            red_rel_add(&g_bar, 1u);
            const unsigned target = (t + 1u) * (unsigned)P_CTAS;
            while (ld_acq(&g_bar) < target) { }
        }
        __syncthreads();
    }
}

// ---------------------------------------------------------------------------
extern "C" void kernel_launch(void* const* d_in, const int* in_sizes, int n_in,
                              void* d_out, int out_size)
{
    const float* x  = (const float*)d_in[0];   // (64, 512, 1024)
    const float* h0 = (const float*)d_in[1];   // (64, 1024)
    const float* Wx = (const float*)d_in[2];   // (1024, 4096)
    const float* Wh = (const float*)d_in[3];   // (1024, 4096)
    const float* b  = (const float*)d_in[4];   // (4096,)
    float* out = (float*)d_out;                // (64, 512, 1024)

    cudaFuncSetAttribute(xw_gemm_mma,     cudaFuncAttributeMaxDynamicSharedMemorySize, G_SMEM);
    cudaFuncSetAttribute(lstm_persistent, cudaFuncAttributeMaxDynamicSharedMemorySize, P_SMEM);

    __half *wxt_hi, *wxt_lo, *wht_hi, *wht_lo;
    cudaGetSymbolAddress((void**)&wxt_hi, g_wxt_hi);
    cudaGetSymbolAddress((void**)&wxt_lo, g_wxt_lo);
    cudaGetSymbolAddress((void**)&wht_hi, g_wht_hi);
    cudaGetSymbolAddress((void**)&wht_lo, g_wht_lo);

    prep_small_kernel<<<64, 1024>>>(h0, b);
    split_x_kernel<<<(NB * TT * DD / 4) / 256, 256>>>(x);
    transpose_split_kernel<<<dim3(DD / 32, FOURH / 32), dim3(32, 8)>>>(Wx, wxt_hi, wxt_lo);
    transpose_split_kernel<<<dim3(DD / 32, FOURH / 32), dim3(32, 8)>>>(Wh, wht_hi, wht_lo);

    xw_gemm_mma<<<dim3(32, 256), 256, G_SMEM>>>();

    lstm_persistent<<<P_CTAS, 256, P_SMEM>>>(out);
}

// round 14
// speedup vs baseline: 2.0751x; 1.4133x over previous
#include <cuda_runtime.h>
#include <cuda_fp16.h>
#include <math.h>
#include <stdint.h>

#define NB 64
#define TT 512
#define DD 1024
#define HH 1024
#define FOURH 4096
#define P_CTAS 128

// ---------------------------------------------------------------------------
// Scratch (__device__ globals; allocation-free rule)
// ---------------------------------------------------------------------------
__device__ float    g_xw[(size_t)NB * TT * FOURH];      // 512 MiB xW+b (permuted cols)
__device__ __half   g_xh[(size_t)NB * TT * DD];         // 64 MiB x fp16
__device__ __half   g_wxt[(size_t)FOURH * DD];          // WxT perm [j'][k] fp16
__device__ __half   g_wht[(size_t)FOURH * DD];          // WhT perm [j'][k] fp16
__device__ __half   g_h[2][NB * HH];                    // h double buffer (fp16)
__device__ float    g_biasp[FOURH];                     // permuted bias
__device__ unsigned g_bar;                              // global barrier counter

// ---------------------------------------------------------------------------
// Helpers
// ---------------------------------------------------------------------------
__device__ __forceinline__ uint32_t smem_u32(const void* p) {
    uint32_t a;
    asm("{ .reg .u64 t; cvta.to.shared.u64 t, %1; cvt.u32.u64 %0, t; }"
        : "=r"(a) : "l"(p));
    return a;
}
__device__ __forceinline__ unsigned ld_acq(const unsigned* p) {
    unsigned v;
    asm volatile("ld.global.acquire.gpu.u32 %0, [%1];" : "=r"(v) : "l"(p) : "memory");
    return v;
}
__device__ __forceinline__ void red_rel_add(unsigned* p, unsigned v) {
    asm volatile("red.release.gpu.global.add.u32 [%0], %1;" :: "l"(p), "r"(v) : "memory");
}

#define CP16(dst, src) \
    asm volatile("cp.async.cg.shared.global [%0], [%1], 16;" :: "r"(dst), "l"(src) : "memory")
#define CP_COMMIT() asm volatile("cp.async.commit_group;" ::: "memory")
#define CP_WAIT(n)  asm volatile("cp.async.wait_group %0;" :: "n"(n) : "memory")

#define LDSM4(r0, r1, r2, r3, addr) \
    asm volatile("ldmatrix.sync.aligned.m8n8.x4.shared.b16 {%0,%1,%2,%3}, [%4];" \
                 : "=r"(r0), "=r"(r1), "=r"(r2), "=r"(r3) : "r"(addr))

#define MMA_F16(c0, c1, c2, c3, a0, a1, a2, a3, b0, b1) \
    asm volatile("mma.sync.aligned.m16n8k16.row.col.f32.f16.f16.f32 " \
                 "{%0,%1,%2,%3}, {%4,%5,%6,%7}, {%8,%9}, {%0,%1,%2,%3};" \
                 : "+f"(c0), "+f"(c1), "+f"(c2), "+f"(c3) \
                 : "r"(a0), "r"(a1), "r"(a2), "r"(a3), "r"(b0), "r"(b1))

__device__ __forceinline__ float fsigmoid(float x) { return 1.0f / (1.0f + __expf(-x)); }
__device__ __forceinline__ float ftanh(float x)    { return 2.0f / (1.0f + __expf(-2.0f * x)) - 1.0f; }

// ---------------------------------------------------------------------------
// Prep kernels
// ---------------------------------------------------------------------------
__global__ void prep_small_kernel(const float* __restrict__ h0, const float* __restrict__ b) {
    int i = blockIdx.x * 1024 + threadIdx.x;
    if (i == 0) g_bar = 0u;
    if (i < NB * HH) {
        g_h[0][i] = __float2half_rn(h0[i]);
    }
    if (i < FOURH) {
        int jp = (i & 1023) * 4 + (i >> 10);     // perm: col g*1024+jh -> jh*4+g
        g_biasp[jp] = b[i];
    }
}

__global__ void split_x_kernel(const float* __restrict__ x) {
    size_t i = ((size_t)blockIdx.x * 256 + threadIdx.x) * 4;
    float4 v = *(const float4*)(x + i);
    __half2* ph = (__half2*)(g_xh + i);
    ph[0] = __floats2half2_rn(v.x, v.y);
    ph[1] = __floats2half2_rn(v.z, v.w);
}

// W (1024 x 4096, k-major rows) -> out[j'][k] fp16 with gate permutation.
__global__ void transpose_perm_kernel(const float* __restrict__ W,
                                      __half* __restrict__ o) {
    __shared__ float ts[32][33];
    const int k0 = blockIdx.x * 32;
    const int c0 = blockIdx.y * 32;
    const int tx = threadIdx.x, ty = threadIdx.y;  // 32 x 8
    #pragma unroll
    for (int i = 0; i < 4; i++)
        ts[ty + 8 * i][tx] = W[(size_t)(k0 + ty + 8 * i) * FOURH + c0 + tx];
    __syncthreads();
    #pragma unroll
    for (int i = 0; i < 4; i++) {
        int c = c0 + ty + 8 * i;
        int jp = (c & 1023) * 4 + (c >> 10);
        o[(size_t)jp * DD + k0 + tx] = __float2half_rn(ts[tx][ty + 8 * i]);
    }
}

// ---------------------------------------------------------------------------
// xW GEMM via mma.sync, single fp16 term: g_xw[token][j'] = x @ WxT^T + b
// CTA tile 128(token) x 128(j'), k-chunk 64, 3-stage cp.async pipeline.
// ---------------------------------------------------------------------------
#define G_STAGE 32768   // A 16K | B 16K
#define G_SMEM  (3 * G_STAGE)

__global__ __launch_bounds__(256, 1)
void xw_gemm_mma() {
    extern __shared__ char smem[];
    const uint32_t sb = smem_u32(smem);
    const int tid = threadIdx.x;
    const int nbase = blockIdx.x * 128;
    const int mbase = blockIdx.y * 128;

    const __half* Ag = g_xh + (size_t)mbase * DD;
    const __half* Bg = g_wxt + (size_t)nbase * DD;

    auto cp_chunk = [&](int c, int st) {
        const int k0 = c * 64;
        const uint32_t ah = sb + st * G_STAGE;
        #pragma unroll
        for (int i = 0; i < 4; i++) {
            int idx = tid + i * 256;
            int row = idx >> 3, ch = idx & 7;
            uint32_t o = (uint32_t)(row * 128) + (uint32_t)((ch * 16) ^ ((row & 7) * 16));
            CP16(ah + o,         (const char*)(Ag + (size_t)row * DD + k0) + ch * 16);
            CP16(ah + 16384 + o, (const char*)(Bg + (size_t)row * DD + k0) + ch * 16);
        }
        CP_COMMIT();
    };

    const int wid = tid >> 5, lane = tid & 31;
    const int wm = wid >> 2, wn = wid & 3;      // warp grid 2x4
    const int m0 = wm * 64, n0 = wn * 32;
    const int gid = lane >> 2, tig = lane & 3;

    const int a_r = lane & 15;
    const uint32_t a_k = ((lane >> 4) & 1) * 16;
    const uint32_t a_x = (uint32_t)((a_r & 7) * 16);
    const int b_r = (lane & 7) + ((lane >> 4) & 1) * 8;
    const uint32_t b_k = ((lane >> 3) & 1) * 16;
    const uint32_t b_x = (uint32_t)((lane & 7) * 16);

    float acc[4][4][4];
    #pragma unroll
    for (int mt = 0; mt < 4; mt++)
        #pragma unroll
        for (int nt = 0; nt < 4; nt++)
            #pragma unroll
            for (int q = 0; q < 4; q++) acc[mt][nt][q] = 0.0f;

    cp_chunk(0, 0);
    cp_chunk(1, 1);

    for (int c = 0; c < 16; c++) {
        if (c + 2 < 16) { cp_chunk(c + 2, (c + 2) % 3); CP_WAIT(2); }
        else if (c + 1 < 16) { CP_WAIT(1); }
        else { CP_WAIT(0); }
        __syncthreads();

        const uint32_t base = sb + (c % 3) * G_STAGE;
        #pragma unroll
        for (int kk = 0; kk < 4; kk++) {
            const uint32_t ka = ((uint32_t)(kk * 32) + a_k) ^ a_x;
            const uint32_t kb = ((uint32_t)(kk * 32) + b_k) ^ b_x;
            uint32_t a[4][4], bh[2][4];
            #pragma unroll
            for (int mt = 0; mt < 4; mt++) {
                uint32_t ra = base + (uint32_t)((m0 + mt * 16 + a_r) * 128);
                LDSM4(a[mt][0], a[mt][1], a[mt][2], a[mt][3], ra + ka);
            }
            #pragma unroll
            for (int p = 0; p < 2; p++) {
                uint32_t rb = base + 16384 + (uint32_t)((n0 + p * 16 + b_r) * 128);
                LDSM4(bh[p][0], bh[p][1], bh[p][2], bh[p][3], rb + kb);
            }
            #pragma unroll
            for (int mt = 0; mt < 4; mt++)
                #pragma unroll
                for (int nt = 0; nt < 4; nt++) {
                    const int p = nt >> 1, hf = (nt & 1) * 2;
                    MMA_F16(acc[mt][nt][0], acc[mt][nt][1], acc[mt][nt][2], acc[mt][nt][3],
                            a[mt][0], a[mt][1], a[mt][2], a[mt][3],
                            bh[p][hf], bh[p][hf + 1]);
                }
        }
        __syncthreads();
    }

    #pragma unroll
    for (int nt = 0; nt < 4; nt++) {
        const int col = nbase + n0 + nt * 8 + tig * 2;
        float2 bv = *(const float2*)&g_biasp[col];
        #pragma unroll
        for (int mt = 0; mt < 4; mt++) {
            const int row = mbase + m0 + mt * 16 + gid;
            float2 v0, v1;
            v0.x = acc[mt][nt][0] + bv.x; v0.y = acc[mt][nt][1] + bv.y;
            v1.x = acc[mt][nt][2] + bv.x; v1.y = acc[mt][nt][3] + bv.y;
            *(float2*)&g_xw[(size_t)row * FOURH + col] = v0;
            *(float2*)&g_xw[(size_t)(row + 8) * FOURH + col] = v1;
        }
    }
}

// ---------------------------------------------------------------------------
// Persistent LSTM recurrence, single fp16 term: D = Wh . h^T.
// 128 CTAs x 256 threads. CTA jb owns j' [jb*32, jb*32+32). Warp w owns batch
// rows [w*8, w*8+8). Wh resident in SMEM (64KB); h fp16 streamed.
// One cheap global barrier per step; chunk order rotated by jb>>3.
// ---------------------------------------------------------------------------
#define PA     0                 // 64KB Wh slice, 16 chunks x 4KB
#define PB     65536             // 4 stages x 8KB (h fp16)
#define PXW    98304             // 8KB xw tile (64 n x 32 j')
#define PASW   106496            // 8 warps x 1152B staging
#define P_SMEM (106496 + 9216)

__global__ __launch_bounds__(256, 1)
void lstm_persistent(float* __restrict__ out) {
    extern __shared__ char smem[];
    const uint32_t sb = smem_u32(smem);
    const int tid = threadIdx.x;
    const int jb = blockIdx.x;                 // 0..127
    const int wid = tid >> 5, lane = tid & 31;
    const int n0 = wid * 8;                    // warp's batch rows
    const int gid = lane >> 2, tig = lane & 3;
    const int rot = jb >> 3;                   // chunk-order rotation

    // A (Wh) ldmatrix addressing
    const int a_r = lane & 15;
    const uint32_t a_k = ((lane >> 4) & 1) * 16;
    const uint32_t a_x = (uint32_t)((a_r & 7) * 16);
    // B ldmatrix addressing (n8 x k32 via x4)
    const int b_row = lane & 7;
    const int b_mat = lane >> 3;

    // ---- load persistent Wh slice (16 k-chunks x 32 rows x 128B) ----
    {
        const __half* Ahg = g_wht + (size_t)jb * 32 * DD;
        #pragma unroll
        for (int i = 0; i < 16; i++) {
            int idx = tid + i * 256;
            int c = idx >> 8;
            int row = (idx >> 3) & 31;
            int ch = idx & 7;
            uint32_t o = (uint32_t)(c * 4096 + row * 128)
                       + (uint32_t)((ch * 16) ^ ((row & 7) * 16));
            CP16(sb + PA + o, (const char*)(Ahg + (size_t)row * DD + c * 64) + ch * 16);
        }
        CP_COMMIT();
        CP_WAIT(0);
        __syncthreads();
    }

    float creg[2] = {0.0f, 0.0f};

    for (unsigned t = 0; t < TT; t++) {
        const __half* Bg = g_h[t & 1];

        // warp-private B chunk load: 8 rows x 64 k fp16, 2 cp/lane
        auto cp_b = [&](int c, int st) {
            const int k0 = c * 64;
            const uint32_t bb = sb + PB + (uint32_t)(st * 8192);
            #pragma unroll
            for (int q = 0; q < 2; q++) {
                int idx = lane + q * 32;      // 0..63
                int row = idx >> 3;           // 0..7
                int ch = idx & 7;
                uint32_t o = (uint32_t)((n0 + row) * 128) + (uint32_t)((ch * 16) ^ (row * 16));
                CP16(bb + o, (const char*)(Bg + (size_t)(n0 + row) * DD + k0) + ch * 16);
            }
        };

        // group 0: warp's xw rows + B chunk (rot)
        #pragma unroll
        for (int q = 0; q < 2; q++) {
            int idx = lane + q * 32;
            int row = idx >> 3, ch = idx & 7;
            CP16(sb + PXW + (uint32_t)((n0 + row) * 128 + ch * 16),
                 (const char*)(g_xw + ((size_t)(n0 + row) * TT + t) * FOURH + jb * 32) + ch * 16);
        }
        cp_b(rot, 0);              CP_COMMIT();
        cp_b((1 + rot) & 15, 1);   CP_COMMIT();
        cp_b((2 + rot) & 15, 2);   CP_COMMIT();

        float acc[2][4];
        #pragma unroll
        for (int mt = 0; mt < 2; mt++)
            #pragma unroll
            for (int q = 0; q < 4; q++) acc[mt][q] = 0.0f;

        for (int cc = 0; cc < 16; cc++) {
            if (cc + 3 < 16) {
                cp_b((cc + 3 + rot) & 15, (cc + 3) & 3);
                CP_COMMIT(); CP_WAIT(3);
            }
            else if (cc == 13)   { CP_WAIT(2); }
            else if (cc == 14)   { CP_WAIT(1); }
            else                 { CP_WAIT(0); }
            __syncwarp();

            const int c = (cc + rot) & 15;
            const uint32_t bst = sb + PB + (uint32_t)((cc & 3) * 8192);
            const uint32_t ahc = sb + PA + (uint32_t)(c * 4096);
            #pragma unroll
            for (int k2 = 0; k2 < 2; k2++) {
                uint32_t bh[4];
                const uint32_t bo = (uint32_t)((n0 + b_row) * 128)
                                  + (uint32_t)((k2 * 64 + b_mat * 16) ^ (b_row * 16));
                LDSM4(bh[0], bh[1], bh[2], bh[3], bst + bo);
                #pragma unroll
                for (int hf = 0; hf < 2; hf++) {
                    const int kk = k2 * 2 + hf;
                    const uint32_t ka = ((uint32_t)(kk * 32) + a_k) ^ a_x;
                    #pragma unroll
                    for (int mt = 0; mt < 2; mt++) {
                        uint32_t ah[4];
                        const uint32_t ao = (uint32_t)((mt * 16 + a_r) * 128) + ka;
                        LDSM4(ah[0], ah[1], ah[2], ah[3], ahc + ao);
                        MMA_F16(acc[mt][0], acc[mt][1], acc[mt][2], acc[mt][3],
                                ah[0], ah[1], ah[2], ah[3], bh[hf * 2], bh[hf * 2 + 1]);
                    }
                }
            }
        }

        // warp-local epilogue: stage acc -> asw[n_local][j'] (stride 36), gates
        float* asw = (float*)(smem + PASW + wid * 1152);
        #pragma unroll
        for (int mt = 0; mt < 2; mt++) {
            asw[(tig * 2 + 0) * 36 + mt * 16 + gid]     = acc[mt][0];
            asw[(tig * 2 + 1) * 36 + mt * 16 + gid]     = acc[mt][1];
            asw[(tig * 2 + 0) * 36 + mt * 16 + gid + 8] = acc[mt][2];
            asw[(tig * 2 + 1) * 36 + mt * 16 + gid + 8] = acc[mt][3];
        }
        __syncwarp();

        {
            const float* xws = (const float*)(smem + PXW);
            __half* nh = g_h[(t + 1) & 1];
            #pragma unroll
            for (int i = 0; i < 2; i++) {
                const int p = lane + i * 32;    // 0..63
                const int nl = p >> 3;          // 0..7
                const int jhl = p & 7;          // 0..7
                const float* ar = asw + nl * 36 + jhl * 4;
                const float* xr = xws + (n0 + nl) * 32 + jhl * 4;
                float ig = fsigmoid(ar[0] + xr[0]);
                float fg = fsigmoid(ar[1] + xr[1]);
                float og = fsigmoid(ar[2] + xr[2]);
                float gg = ftanh(ar[3] + xr[3]);
                float cn = fg * creg[i] + ig * gg;
                creg[i] = cn;
                float h = og * ftanh(cn);
                const int n = n0 + nl;
                const int jg = jb * 8 + jhl;
                out[((size_t)n * TT + t) * HH + jg] = h;
                nh[n * HH + jg] = __float2half_rn(h);
            }
        }

        // cheap global barrier: release-add publish, acquire poll (tid 0 only)
        __syncthreads();
        if (tid == 0) {
            red_rel_add(&g_bar, 1u);
            const unsigned target = (t + 1u) * (unsigned)P_CTAS;
            while (ld_acq(&g_bar) < target) { }
        }
        __syncthreads();
    }
}

// ---------------------------------------------------------------------------
extern "C" void kernel_launch(void* const* d_in, const int* in_sizes, int n_in,
                              void* d_out, int out_size)
{
    const float* x  = (const float*)d_in[0];   // (64, 512, 1024)
    const float* h0 = (const float*)d_in[1];   // (64, 1024)
    const float* Wx = (const float*)d_in[2];   // (1024, 4096)
    const float* Wh = (const float*)d_in[3];   // (1024, 4096)
    const float* b  = (const float*)d_in[4];   // (4096,)
    float* out = (float*)d_out;                // (64, 512, 1024)

    cudaFuncSetAttribute(xw_gemm_mma,     cudaFuncAttributeMaxDynamicSharedMemorySize, G_SMEM);
    cudaFuncSetAttribute(lstm_persistent, cudaFuncAttributeMaxDynamicSharedMemorySize, P_SMEM);

    __half *wxt, *wht;
    cudaGetSymbolAddress((void**)&wxt, g_wxt);
    cudaGetSymbolAddress((void**)&wht, g_wht);

    prep_small_kernel<<<64, 1024>>>(h0, b);
    split_x_kernel<<<(NB * TT * DD / 4) / 256, 256>>>(x);
    transpose_perm_kernel<<<dim3(DD / 32, FOURH / 32), dim3(32, 8)>>>(Wx, wxt);
    transpose_perm_kernel<<<dim3(DD / 32, FOURH / 32), dim3(32, 8)>>>(Wh, wht);

    xw_gemm_mma<<<dim3(32, 256), 256, G_SMEM>>>();

    lstm_persistent<<<P_CTAS, 256, P_SMEM>>>(out);
}

// round 15
// speedup vs baseline: 2.0944x; 1.0093x over previous
#include <cuda_runtime.h>
#include <cuda_fp16.h>
#include <math.h>
#include <stdint.h>

#define NB 64
#define TT 512
#define DD 1024
#define HH 1024
#define FOURH 4096
#define P_CTAS 128

// ---------------------------------------------------------------------------
// Scratch (__device__ globals; allocation-free rule)
// ---------------------------------------------------------------------------
__device__ __half   g_xw[(size_t)NB * TT * FOURH];      // 256 MiB xW+b fp16 (permuted cols)
__device__ __half   g_xh[(size_t)NB * TT * DD];         // 64 MiB x fp16
__device__ __half   g_wxt[(size_t)FOURH * DD];          // WxT perm [j'][k] fp16
__device__ __half   g_wht[(size_t)FOURH * DD];          // WhT perm [j'][k] fp16
__device__ __half   g_h[2][NB * HH];                    // h double buffer (fp16)
__device__ float    g_biasp[FOURH];                     // permuted bias
__device__ unsigned g_bar;                              // global barrier counter

// ---------------------------------------------------------------------------
// Helpers
// ---------------------------------------------------------------------------
__device__ __forceinline__ uint32_t smem_u32(const void* p) {
    uint32_t a;
    asm("{ .reg .u64 t; cvta.to.shared.u64 t, %1; cvt.u32.u64 %0, t; }"
        : "=r"(a) : "l"(p));
    return a;
}
__device__ __forceinline__ unsigned ld_acq(const unsigned* p) {
    unsigned v;
    asm volatile("ld.global.acquire.gpu.u32 %0, [%1];" : "=r"(v) : "l"(p) : "memory");
    return v;
}
__device__ __forceinline__ void red_rel_add(unsigned* p, unsigned v) {
    asm volatile("red.release.gpu.global.add.u32 [%0], %1;" :: "l"(p), "r"(v) : "memory");
}

#define CP16(dst, src) \
    asm volatile("cp.async.cg.shared.global [%0], [%1], 16;" :: "r"(dst), "l"(src) : "memory")
#define CP_COMMIT() asm volatile("cp.async.commit_group;" ::: "memory")
#define CP_WAIT(n)  asm volatile("cp.async.wait_group %0;" :: "n"(n) : "memory")

#define LDSM4(r0, r1, r2, r3, addr) \
    asm volatile("ldmatrix.sync.aligned.m8n8.x4.shared.b16 {%0,%1,%2,%3}, [%4];" \
                 : "=r"(r0), "=r"(r1), "=r"(r2), "=r"(r3) : "r"(addr))

#define MMA_F16(c0, c1, c2, c3, a0, a1, a2, a3, b0, b1) \
    asm volatile("mma.sync.aligned.m16n8k16.row.col.f32.f16.f16.f32 " \
                 "{%0,%1,%2,%3}, {%4,%5,%6,%7}, {%8,%9}, {%0,%1,%2,%3};" \
                 : "+f"(c0), "+f"(c1), "+f"(c2), "+f"(c3) \
                 : "r"(a0), "r"(a1), "r"(a2), "r"(a3), "r"(b0), "r"(b1))

__device__ __forceinline__ float fsigmoid(float x) { return 1.0f / (1.0f + __expf(-x)); }
__device__ __forceinline__ float ftanh(float x)    { return 2.0f / (1.0f + __expf(-2.0f * x)) - 1.0f; }

// ---------------------------------------------------------------------------
// Prep kernels
// ---------------------------------------------------------------------------
__global__ void prep_small_kernel(const float* __restrict__ h0, const float* __restrict__ b) {
    int i = blockIdx.x * 1024 + threadIdx.x;
    if (i == 0) g_bar = 0u;
    if (i < NB * HH) {
        g_h[0][i] = __float2half_rn(h0[i]);
    }
    if (i < FOURH) {
        int jp = (i & 1023) * 4 + (i >> 10);     // perm: col g*1024+jh -> jh*4+g
        g_biasp[jp] = b[i];
    }
}

__global__ void split_x_kernel(const float* __restrict__ x) {
    size_t i = ((size_t)blockIdx.x * 256 + threadIdx.x) * 4;
    float4 v = *(const float4*)(x + i);
    __half2* ph = (__half2*)(g_xh + i);
    ph[0] = __floats2half2_rn(v.x, v.y);
    ph[1] = __floats2half2_rn(v.z, v.w);
}

// W (1024 x 4096, k-major rows) -> out[j'][k] fp16 with gate permutation.
__global__ void transpose_perm_kernel(const float* __restrict__ W,
                                      __half* __restrict__ o) {
    __shared__ float ts[32][33];
    const int k0 = blockIdx.x * 32;
    const int c0 = blockIdx.y * 32;
    const int tx = threadIdx.x, ty = threadIdx.y;  // 32 x 8
    #pragma unroll
    for (int i = 0; i < 4; i++)
        ts[ty + 8 * i][tx] = W[(size_t)(k0 + ty + 8 * i) * FOURH + c0 + tx];
    __syncthreads();
    #pragma unroll
    for (int i = 0; i < 4; i++) {
        int c = c0 + ty + 8 * i;
        int jp = (c & 1023) * 4 + (c >> 10);
        o[(size_t)jp * DD + k0 + tx] = __float2half_rn(ts[tx][ty + 8 * i]);
    }
}

// ---------------------------------------------------------------------------
// xW GEMM via mma.sync, single fp16 term: g_xw[token][j'] = fp16(x @ WxT^T + b)
// CTA tile 128(token) x 128(j'), k-chunk 64, 3-stage cp.async pipeline.
// ---------------------------------------------------------------------------
#define G_STAGE 32768   // A 16K | B 16K
#define G_SMEM  (3 * G_STAGE)

__global__ __launch_bounds__(256, 1)
void xw_gemm_mma() {
    extern __shared__ char smem[];
    const uint32_t sb = smem_u32(smem);
    const int tid = threadIdx.x;
    const int nbase = blockIdx.x * 128;
    const int mbase = blockIdx.y * 128;

    const __half* Ag = g_xh + (size_t)mbase * DD;
    const __half* Bg = g_wxt + (size_t)nbase * DD;

    auto cp_chunk = [&](int c, int st) {
        const int k0 = c * 64;
        const uint32_t ah = sb + st * G_STAGE;
        #pragma unroll
        for (int i = 0; i < 4; i++) {
            int idx = tid + i * 256;
            int row = idx >> 3, ch = idx & 7;
            uint32_t o = (uint32_t)(row * 128) + (uint32_t)((ch * 16) ^ ((row & 7) * 16));
            CP16(ah + o,         (const char*)(Ag + (size_t)row * DD + k0) + ch * 16);
            CP16(ah + 16384 + o, (const char*)(Bg + (size_t)row * DD + k0) + ch * 16);
        }
        CP_COMMIT();
    };

    const int wid = tid >> 5, lane = tid & 31;
    const int wm = wid >> 2, wn = wid & 3;      // warp grid 2x4
    const int m0 = wm * 64, n0 = wn * 32;
    const int gid = lane >> 2, tig = lane & 3;

    const int a_r = lane & 15;
    const uint32_t a_k = ((lane >> 4) & 1) * 16;
    const uint32_t a_x = (uint32_t)((a_r & 7) * 16);
    const int b_r = (lane & 7) + ((lane >> 4) & 1) * 8;
    const uint32_t b_k = ((lane >> 3) & 1) * 16;
    const uint32_t b_x = (uint32_t)((lane & 7) * 16);

    float acc[4][4][4];
    #pragma unroll
    for (int mt = 0; mt < 4; mt++)
        #pragma unroll
        for (int nt = 0; nt < 4; nt++)
            #pragma unroll
            for (int q = 0; q < 4; q++) acc[mt][nt][q] = 0.0f;

    cp_chunk(0, 0);
    cp_chunk(1, 1);

    for (int c = 0; c < 16; c++) {
        if (c + 2 < 16) { cp_chunk(c + 2, (c + 2) % 3); CP_WAIT(2); }
        else if (c + 1 < 16) { CP_WAIT(1); }
        else { CP_WAIT(0); }
        __syncthreads();

        const uint32_t base = sb + (c % 3) * G_STAGE;
        #pragma unroll
        for (int kk = 0; kk < 4; kk++) {
            const uint32_t ka = ((uint32_t)(kk * 32) + a_k) ^ a_x;
            const uint32_t kb = ((uint32_t)(kk * 32) + b_k) ^ b_x;
            uint32_t a[4][4], bh[2][4];
            #pragma unroll
            for (int mt = 0; mt < 4; mt++) {
                uint32_t ra = base + (uint32_t)((m0 + mt * 16 + a_r) * 128);
                LDSM4(a[mt][0], a[mt][1], a[mt][2], a[mt][3], ra + ka);
            }
            #pragma unroll
            for (int p = 0; p < 2; p++) {
                uint32_t rb = base + 16384 + (uint32_t)((n0 + p * 16 + b_r) * 128);
                LDSM4(bh[p][0], bh[p][1], bh[p][2], bh[p][3], rb + kb);
            }
            #pragma unroll
            for (int mt = 0; mt < 4; mt++)
                #pragma unroll
                for (int nt = 0; nt < 4; nt++) {
                    const int p = nt >> 1, hf = (nt & 1) * 2;
                    MMA_F16(acc[mt][nt][0], acc[mt][nt][1], acc[mt][nt][2], acc[mt][nt][3],
                            a[mt][0], a[mt][1], a[mt][2], a[mt][3],
                            bh[p][hf], bh[p][hf + 1]);
                }
        }
        __syncthreads();
    }

    #pragma unroll
    for (int nt = 0; nt < 4; nt++) {
        const int col = nbase + n0 + nt * 8 + tig * 2;
        float2 bv = *(const float2*)&g_biasp[col];
        #pragma unroll
        for (int mt = 0; mt < 4; mt++) {
            const int row = mbase + m0 + mt * 16 + gid;
            __half2 v0 = __floats2half2_rn(acc[mt][nt][0] + bv.x, acc[mt][nt][1] + bv.y);
            __half2 v1 = __floats2half2_rn(acc[mt][nt][2] + bv.x, acc[mt][nt][3] + bv.y);
            *(__half2*)&g_xw[(size_t)row * FOURH + col] = v0;
            *(__half2*)&g_xw[(size_t)(row + 8) * FOURH + col] = v1;
        }
    }
}

// ---------------------------------------------------------------------------
// Persistent LSTM recurrence, single fp16 term: D = Wh . h^T.
// 128 CTAs x 256 threads. CTA jb owns j' [jb*32, jb*32+32). Warp w owns batch
// rows [w*8, w*8+8). Wh resident in SMEM (64KB); h fp16 streamed.
// 4 independent accumulator chains per warp (k16-parity split) to cover HMMA
// latency. One cheap global barrier per step; chunk order rotated by jb>>3.
// ---------------------------------------------------------------------------
#define PA     0                 // 64KB Wh slice, 16 chunks x 4KB
#define PB     65536             // 4 stages x 8KB (h fp16)
#define PXW    98304             // 4KB xw tile (64 n x 32 j' fp16)
#define PASW   102400            // 8 warps x 1152B staging
#define P_SMEM (102400 + 9216)

__global__ __launch_bounds__(256, 1)
void lstm_persistent(float* __restrict__ out) {
    extern __shared__ char smem[];
    const uint32_t sb = smem_u32(smem);
    const int tid = threadIdx.x;
    const int jb = blockIdx.x;                 // 0..127
    const int wid = tid >> 5, lane = tid & 31;
    const int n0 = wid * 8;                    // warp's batch rows
    const int gid = lane >> 2, tig = lane & 3;
    const int rot = jb >> 3;                   // chunk-order rotation

    // A (Wh) ldmatrix addressing
    const int a_r = lane & 15;
    const uint32_t a_k = ((lane >> 4) & 1) * 16;
    const uint32_t a_x = (uint32_t)((a_r & 7) * 16);
    // B ldmatrix addressing (n8 x k32 via x4)
    const int b_row = lane & 7;
    const int b_mat = lane >> 3;

    // ---- load persistent Wh slice (16 k-chunks x 32 rows x 128B) ----
    {
        const __half* Ahg = g_wht + (size_t)jb * 32 * DD;
        #pragma unroll
        for (int i = 0; i < 16; i++) {
            int idx = tid + i * 256;
            int c = idx >> 8;
            int row = (idx >> 3) & 31;
            int ch = idx & 7;
            uint32_t o = (uint32_t)(c * 4096 + row * 128)
                       + (uint32_t)((ch * 16) ^ ((row & 7) * 16));
            CP16(sb + PA + o, (const char*)(Ahg + (size_t)row * DD + c * 64) + ch * 16);
        }
        CP_COMMIT();
        CP_WAIT(0);
        __syncthreads();
    }

    float creg[2] = {0.0f, 0.0f};

    for (unsigned t = 0; t < TT; t++) {
        const __half* Bg = g_h[t & 1];

        // warp-private B chunk load: 8 rows x 64 k fp16, 2 cp/lane
        auto cp_b = [&](int c, int st) {
            const int k0 = c * 64;
            const uint32_t bb = sb + PB + (uint32_t)(st * 8192);
            #pragma unroll
            for (int q = 0; q < 2; q++) {
                int idx = lane + q * 32;      // 0..63
                int row = idx >> 3;           // 0..7
                int ch = idx & 7;
                uint32_t o = (uint32_t)((n0 + row) * 128) + (uint32_t)((ch * 16) ^ (row * 16));
                CP16(bb + o, (const char*)(Bg + (size_t)(n0 + row) * DD + k0) + ch * 16);
            }
        };

        // group 0: warp's xw rows (fp16, 8 rows x 64B) + B chunk (rot)
        {
            int row = lane >> 2, ch = lane & 3;
            CP16(sb + PXW + (uint32_t)(wid * 512 + row * 64 + ch * 16),
                 (const char*)(g_xw + ((size_t)(n0 + row) * TT + t) * FOURH + jb * 32) + ch * 16);
        }
        cp_b(rot, 0);              CP_COMMIT();
        cp_b((1 + rot) & 15, 1);   CP_COMMIT();
        cp_b((2 + rot) & 15, 2);   CP_COMMIT();

        // 4 independent accumulator chains: [mt][k16-parity]
        float accE[2][4], accO[2][4];
        #pragma unroll
        for (int mt = 0; mt < 2; mt++)
            #pragma unroll
            for (int q = 0; q < 4; q++) { accE[mt][q] = 0.0f; accO[mt][q] = 0.0f; }

        for (int cc = 0; cc < 16; cc++) {
            if (cc + 3 < 16) {
                cp_b((cc + 3 + rot) & 15, (cc + 3) & 3);
                CP_COMMIT(); CP_WAIT(3);
            }
            else if (cc == 13)   { CP_WAIT(2); }
            else if (cc == 14)   { CP_WAIT(1); }
            else                 { CP_WAIT(0); }
            __syncwarp();

            const int c = (cc + rot) & 15;
            const uint32_t bst = sb + PB + (uint32_t)((cc & 3) * 8192);
            const uint32_t ahc = sb + PA + (uint32_t)(c * 4096);
            #pragma unroll
            for (int k2 = 0; k2 < 2; k2++) {
                uint32_t bh[4];
                const uint32_t bo = (uint32_t)((n0 + b_row) * 128)
                                  + (uint32_t)((k2 * 64 + b_mat * 16) ^ (b_row * 16));
                LDSM4(bh[0], bh[1], bh[2], bh[3], bst + bo);
                uint32_t a0[2][4], a1[2][4];
                #pragma unroll
                for (int mt = 0; mt < 2; mt++) {
                    const uint32_t ka0 = ((uint32_t)(k2 * 64) + a_k) ^ a_x;
                    const uint32_t ka1 = ((uint32_t)(k2 * 64 + 32) + a_k) ^ a_x;
                    const uint32_t ar = (uint32_t)((mt * 16 + a_r) * 128);
                    LDSM4(a0[mt][0], a0[mt][1], a0[mt][2], a0[mt][3], ahc + ar + ka0);
                    LDSM4(a1[mt][0], a1[mt][1], a1[mt][2], a1[mt][3], ahc + ar + ka1);
                }
                // hf=0 -> accE chains, hf=1 -> accO chains (4-issue dependent spacing)
                #pragma unroll
                for (int mt = 0; mt < 2; mt++)
                    MMA_F16(accE[mt][0], accE[mt][1], accE[mt][2], accE[mt][3],
                            a0[mt][0], a0[mt][1], a0[mt][2], a0[mt][3], bh[0], bh[1]);
                #pragma unroll
                for (int mt = 0; mt < 2; mt++)
                    MMA_F16(accO[mt][0], accO[mt][1], accO[mt][2], accO[mt][3],
                            a1[mt][0], a1[mt][1], a1[mt][2], a1[mt][3], bh[2], bh[3]);
            }
        }

        // merge chains, stage acc -> asw[n_local][j'] (stride 36), gates
        float* asw = (float*)(smem + PASW + wid * 1152);
        #pragma unroll
        for (int mt = 0; mt < 2; mt++) {
            asw[(tig * 2 + 0) * 36 + mt * 16 + gid]     = accE[mt][0] + accO[mt][0];
            asw[(tig * 2 + 1) * 36 + mt * 16 + gid]     = accE[mt][1] + accO[mt][1];
            asw[(tig * 2 + 0) * 36 + mt * 16 + gid + 8] = accE[mt][2] + accO[mt][2];
            asw[(tig * 2 + 1) * 36 + mt * 16 + gid + 8] = accE[mt][3] + accO[mt][3];
        }
        __syncwarp();

        {
            const __half* xws = (const __half*)(smem + PXW) + wid * 256;
            __half* nh = g_h[(t + 1) & 1];
            #pragma unroll
            for (int i = 0; i < 2; i++) {
                const int p = lane + i * 32;    // 0..63
                const int nl = p >> 3;          // 0..7
                const int jhl = p & 7;          // 0..7
                const float* ar = asw + nl * 36 + jhl * 4;
                const __half2* xr = (const __half2*)(xws + nl * 32 + jhl * 4);
                float2 x01 = __half22float2(xr[0]);
                float2 x23 = __half22float2(xr[1]);
                float ig = fsigmoid(ar[0] + x01.x);
                float fg = fsigmoid(ar[1] + x01.y);
                float og = fsigmoid(ar[2] + x23.x);
                float gg = ftanh(ar[3] + x23.y);
                float cn = fg * creg[i] + ig * gg;
                creg[i] = cn;
                float h = og * ftanh(cn);
                const int n = n0 + nl;
                const int jg = jb * 8 + jhl;
                out[((size_t)n * TT + t) * HH + jg] = h;
                nh[n * HH + jg] = __float2half_rn(h);
            }
        }

        // cheap global barrier: release-add publish, acquire poll (tid 0 only)
        __syncthreads();
        if (tid == 0) {
            red_rel_add(&g_bar, 1u);
            const unsigned target = (t + 1u) * (unsigned)P_CTAS;
            while (ld_acq(&g_bar) < target) { }
        }
        __syncthreads();
    }
}

// ---------------------------------------------------------------------------
extern "C" void kernel_launch(void* const* d_in, const int* in_sizes, int n_in,
                              void* d_out, int out_size)
{
    const float* x  = (const float*)d_in[0];   // (64, 512, 1024)
    const float* h0 = (const float*)d_in[1];   // (64, 1024)
    const float* Wx = (const float*)d_in[2];   // (1024, 4096)
    const float* Wh = (const float*)d_in[3];   // (1024, 4096)
    const float* b  = (const float*)d_in[4];   // (4096,)
    float* out = (float*)d_out;                // (64, 512, 1024)

    cudaFuncSetAttribute(xw_gemm_mma,     cudaFuncAttributeMaxDynamicSharedMemorySize, G_SMEM);
    cudaFuncSetAttribute(lstm_persistent, cudaFuncAttributeMaxDynamicSharedMemorySize, P_SMEM);

    __half *wxt, *wht;
    cudaGetSymbolAddress((void**)&wxt, g_wxt);
    cudaGetSymbolAddress((void**)&wht, g_wht);

    prep_small_kernel<<<64, 1024>>>(h0, b);
    split_x_kernel<<<(NB * TT * DD / 4) / 256, 256>>>(x);
    transpose_perm_kernel<<<dim3(DD / 32, FOURH / 32), dim3(32, 8)>>>(Wx, wxt);
    transpose_perm_kernel<<<dim3(DD / 32, FOURH / 32), dim3(32, 8)>>>(Wh, wht);

    xw_gemm_mma<<<dim3(32, 256), 256, G_SMEM>>>();

    lstm_persistent<<<P_CTAS, 256, P_SMEM>>>(out);
}

// round 16
// speedup vs baseline: 2.1630x; 1.0328x over previous
#include <cuda_runtime.h>
#include <cuda_fp16.h>
#include <math.h>
#include <stdint.h>

#define NB 64
#define TT 512
#define DD 1024
#define HH 1024
#define FOURH 4096
#define P_CTAS 128

// ---------------------------------------------------------------------------
// Scratch (__device__ globals; allocation-free rule)
// ---------------------------------------------------------------------------
__device__ __half   g_xw[(size_t)NB * TT * FOURH];      // 256 MiB xW+b fp16 (permuted cols)
__device__ __half   g_xh[(size_t)NB * TT * DD];         // 64 MiB x fp16
__device__ __half   g_wxt[(size_t)FOURH * DD];          // WxT perm [j'][k] fp16
__device__ __half   g_wht[(size_t)FOURH * DD];          // WhT perm [j'][k] fp16
__device__ __half   g_h[2][NB * HH];                    // h double buffer (fp16)
__device__ float    g_biasp[FOURH];                     // permuted bias
__device__ unsigned g_bar;                              // global barrier counter

// ---------------------------------------------------------------------------
// Helpers
// ---------------------------------------------------------------------------
__device__ __forceinline__ uint32_t smem_u32(const void* p) {
    uint32_t a;
    asm("{ .reg .u64 t; cvta.to.shared.u64 t, %1; cvt.u32.u64 %0, t; }"
        : "=r"(a) : "l"(p));
    return a;
}
__device__ __forceinline__ unsigned ld_acq(const unsigned* p) {
    unsigned v;
    asm volatile("ld.global.acquire.gpu.u32 %0, [%1];" : "=r"(v) : "l"(p) : "memory");
    return v;
}
__device__ __forceinline__ void red_rel_add(unsigned* p, unsigned v) {
    asm volatile("red.release.gpu.global.add.u32 [%0], %1;" :: "l"(p), "r"(v) : "memory");
}

#define CP16(dst, src) \
    asm volatile("cp.async.cg.shared.global [%0], [%1], 16;" :: "r"(dst), "l"(src) : "memory")
#define CP_COMMIT() asm volatile("cp.async.commit_group;" ::: "memory")
#define CP_WAIT(n)  asm volatile("cp.async.wait_group %0;" :: "n"(n) : "memory")

#define LDSM4(r0, r1, r2, r3, addr) \
    asm volatile("ldmatrix.sync.aligned.m8n8.x4.shared.b16 {%0,%1,%2,%3}, [%4];" \
                 : "=r"(r0), "=r"(r1), "=r"(r2), "=r"(r3) : "r"(addr))

#define MMA_F16(c0, c1, c2, c3, a0, a1, a2, a3, b0, b1) \
    asm volatile("mma.sync.aligned.m16n8k16.row.col.f32.f16.f16.f32 " \
                 "{%0,%1,%2,%3}, {%4,%5,%6,%7}, {%8,%9}, {%0,%1,%2,%3};" \
                 : "+f"(c0), "+f"(c1), "+f"(c2), "+f"(c3) \
                 : "r"(a0), "r"(a1), "r"(a2), "r"(a3), "r"(b0), "r"(b1))

__device__ __forceinline__ float fsigmoid(float x) { return 1.0f / (1.0f + __expf(-x)); }
__device__ __forceinline__ float ftanh(float x)    { return 2.0f / (1.0f + __expf(-2.0f * x)) - 1.0f; }

// ---------------------------------------------------------------------------
// Prep kernels
// ---------------------------------------------------------------------------
__global__ void prep_small_kernel(const float* __restrict__ h0, const float* __restrict__ b) {
    int i = blockIdx.x * 1024 + threadIdx.x;
    if (i == 0) g_bar = 0u;
    if (i < NB * HH) {
        g_h[0][i] = __float2half_rn(h0[i]);
    }
    if (i < FOURH) {
        int jp = (i & 1023) * 4 + (i >> 10);     // perm: col g*1024+jh -> jh*4+g
        g_biasp[jp] = b[i];
    }
}

__global__ void split_x_kernel(const float* __restrict__ x) {
    size_t i = ((size_t)blockIdx.x * 256 + threadIdx.x) * 4;
    float4 v = *(const float4*)(x + i);
    __half2* ph = (__half2*)(g_xh + i);
    ph[0] = __floats2half2_rn(v.x, v.y);
    ph[1] = __floats2half2_rn(v.z, v.w);
}

// W (1024 x 4096, k-major rows) -> out[j'][k] fp16 with gate permutation.
__global__ void transpose_perm_kernel(const float* __restrict__ W,
                                      __half* __restrict__ o) {
    __shared__ float ts[32][33];
    const int k0 = blockIdx.x * 32;
    const int c0 = blockIdx.y * 32;
    const int tx = threadIdx.x, ty = threadIdx.y;  // 32 x 8
    #pragma unroll
    for (int i = 0; i < 4; i++)
        ts[ty + 8 * i][tx] = W[(size_t)(k0 + ty + 8 * i) * FOURH + c0 + tx];
    __syncthreads();
    #pragma unroll
    for (int i = 0; i < 4; i++) {
        int c = c0 + ty + 8 * i;
        int jp = (c & 1023) * 4 + (c >> 10);
        o[(size_t)jp * DD + k0 + tx] = __float2half_rn(ts[tx][ty + 8 * i]);
    }
}

// ---------------------------------------------------------------------------
// xW GEMM via mma.sync, single fp16 term: g_xw[token][j'] = fp16(x @ WxT^T + b)
// CTA tile 128(token) x 128(j'), k-chunk 64, 3-stage cp.async pipeline.
// ---------------------------------------------------------------------------
#define G_STAGE 32768   // A 16K | B 16K
#define G_SMEM  (3 * G_STAGE)

__global__ __launch_bounds__(256, 1)
void xw_gemm_mma() {
    extern __shared__ char smem[];
    const uint32_t sb = smem_u32(smem);
    const int tid = threadIdx.x;
    const int nbase = blockIdx.x * 128;
    const int mbase = blockIdx.y * 128;

    const __half* Ag = g_xh + (size_t)mbase * DD;
    const __half* Bg = g_wxt + (size_t)nbase * DD;

    auto cp_chunk = [&](int c, int st) {
        const int k0 = c * 64;
        const uint32_t ah = sb + st * G_STAGE;
        #pragma unroll
        for (int i = 0; i < 4; i++) {
            int idx = tid + i * 256;
            int row = idx >> 3, ch = idx & 7;
            uint32_t o = (uint32_t)(row * 128) + (uint32_t)((ch * 16) ^ ((row & 7) * 16));
            CP16(ah + o,         (const char*)(Ag + (size_t)row * DD + k0) + ch * 16);
            CP16(ah + 16384 + o, (const char*)(Bg + (size_t)row * DD + k0) + ch * 16);
        }
        CP_COMMIT();
    };

    const int wid = tid >> 5, lane = tid & 31;
    const int wm = wid >> 2, wn = wid & 3;      // warp grid 2x4
    const int m0 = wm * 64, n0 = wn * 32;
    const int gid = lane >> 2, tig = lane & 3;

    const int a_r = lane & 15;
    const uint32_t a_k = ((lane >> 4) & 1) * 16;
    const uint32_t a_x = (uint32_t)((a_r & 7) * 16);
    const int b_r = (lane & 7) + ((lane >> 4) & 1) * 8;
    const uint32_t b_k = ((lane >> 3) & 1) * 16;
    const uint32_t b_x = (uint32_t)((lane & 7) * 16);

    float acc[4][4][4];
    #pragma unroll
    for (int mt = 0; mt < 4; mt++)
        #pragma unroll
        for (int nt = 0; nt < 4; nt++)
            #pragma unroll
            for (int q = 0; q < 4; q++) acc[mt][nt][q] = 0.0f;

    cp_chunk(0, 0);
    cp_chunk(1, 1);

    for (int c = 0; c < 16; c++) {
        if (c + 2 < 16) { cp_chunk(c + 2, (c + 2) % 3); CP_WAIT(2); }
        else if (c + 1 < 16) { CP_WAIT(1); }
        else { CP_WAIT(0); }
        __syncthreads();

        const uint32_t base = sb + (c % 3) * G_STAGE;
        #pragma unroll
        for (int kk = 0; kk < 4; kk++) {
            const uint32_t ka = ((uint32_t)(kk * 32) + a_k) ^ a_x;
            const uint32_t kb = ((uint32_t)(kk * 32) + b_k) ^ b_x;
            uint32_t a[4][4], bh[2][4];
            #pragma unroll
            for (int mt = 0; mt < 4; mt++) {
                uint32_t ra = base + (uint32_t)((m0 + mt * 16 + a_r) * 128);
                LDSM4(a[mt][0], a[mt][1], a[mt][2], a[mt][3], ra + ka);
            }
            #pragma unroll
            for (int p = 0; p < 2; p++) {
                uint32_t rb = base + 16384 + (uint32_t)((n0 + p * 16 + b_r) * 128);
                LDSM4(bh[p][0], bh[p][1], bh[p][2], bh[p][3], rb + kb);
            }
            #pragma unroll
            for (int mt = 0; mt < 4; mt++)
                #pragma unroll
                for (int nt = 0; nt < 4; nt++) {
                    const int p = nt >> 1, hf = (nt & 1) * 2;
                    MMA_F16(acc[mt][nt][0], acc[mt][nt][1], acc[mt][nt][2], acc[mt][nt][3],
                            a[mt][0], a[mt][1], a[mt][2], a[mt][3],
                            bh[p][hf], bh[p][hf + 1]);
                }
        }
        __syncthreads();
    }

    #pragma unroll
    for (int nt = 0; nt < 4; nt++) {
        const int col = nbase + n0 + nt * 8 + tig * 2;
        float2 bv = *(const float2*)&g_biasp[col];
        #pragma unroll
        for (int mt = 0; mt < 4; mt++) {
            const int row = mbase + m0 + mt * 16 + gid;
            __half2 v0 = __floats2half2_rn(acc[mt][nt][0] + bv.x, acc[mt][nt][1] + bv.y);
            __half2 v1 = __floats2half2_rn(acc[mt][nt][2] + bv.x, acc[mt][nt][3] + bv.y);
            *(__half2*)&g_xw[(size_t)row * FOURH + col] = v0;
            *(__half2*)&g_xw[(size_t)(row + 8) * FOURH + col] = v1;
        }
    }
}

// ---------------------------------------------------------------------------
// Persistent LSTM recurrence, single fp16 term: D = Wh . h^T.
// 128 CTAs x 256 threads. CTA jb owns j' [jb*32, jb*32+32). Warp w owns batch
// rows [w*8, w*8+8). Wh resident in SMEM (64KB). NEW: the ENTIRE step's h
// (16 chunks x 8KB) is prefetched into SMEM right after the barrier — load
// latency is paid once per step and overlapped, mainloop is pure issue.
// ---------------------------------------------------------------------------
#define PA     0                 // 64KB Wh slice, 16 chunks x 4KB
#define PB     65536             // 16 stages x 8KB (h fp16) = 128KB
#define PXW    196608            // 4KB xw tile (64 n x 32 j' fp16)
#define PASW   200704            // 8 warps x 1152B staging
#define P_SMEM (200704 + 9216)   // 209920 B

__global__ __launch_bounds__(256, 1)
void lstm_persistent(float* __restrict__ out) {
    extern __shared__ char smem[];
    const uint32_t sb = smem_u32(smem);
    const int tid = threadIdx.x;
    const int jb = blockIdx.x;                 // 0..127
    const int wid = tid >> 5, lane = tid & 31;
    const int n0 = wid * 8;                    // warp's batch rows
    const int gid = lane >> 2, tig = lane & 3;
    const int rot = jb >> 3;                   // chunk-order rotation

    // A (Wh) ldmatrix addressing
    const int a_r = lane & 15;
    const uint32_t a_k = ((lane >> 4) & 1) * 16;
    const uint32_t a_x = (uint32_t)((a_r & 7) * 16);
    // B ldmatrix addressing (n8 x k32 via x4)
    const int b_row = lane & 7;
    const int b_mat = lane >> 3;

    // ---- load persistent Wh slice (16 k-chunks x 32 rows x 128B) ----
    {
        const __half* Ahg = g_wht + (size_t)jb * 32 * DD;
        #pragma unroll
        for (int i = 0; i < 16; i++) {
            int idx = tid + i * 256;
            int c = idx >> 8;
            int row = (idx >> 3) & 31;
            int ch = idx & 7;
            uint32_t o = (uint32_t)(c * 4096 + row * 128)
                       + (uint32_t)((ch * 16) ^ ((row & 7) * 16));
            CP16(sb + PA + o, (const char*)(Ahg + (size_t)row * DD + c * 64) + ch * 16);
        }
        CP_COMMIT();
        CP_WAIT(0);
        __syncthreads();
    }

    float creg[2] = {0.0f, 0.0f};

    // precomputed per-lane offsets for B loads (2 CP16 per chunk per lane)
    const int bl_row0 = lane >> 3;            // rows 0..3 (q=0)
    const int bl_ch0  = lane & 7;
    const int bl_row1 = (lane + 32) >> 3;     // rows 4..7 (q=1)
    const int bl_ch1  = lane & 7;
    const uint32_t bo0 = (uint32_t)((n0 + bl_row0) * 128) + (uint32_t)((bl_ch0 * 16) ^ (bl_row0 * 16));
    const uint32_t bo1 = (uint32_t)((n0 + bl_row1) * 128) + (uint32_t)((bl_ch1 * 16) ^ (bl_row1 * 16));

    for (unsigned t = 0; t < TT; t++) {
        const __half* Bg = g_h[t & 1];

        // ---- fire-and-forget: xw tile + ALL 16 h chunks (one group each) ----
        {
            int row = lane >> 2, ch = lane & 3;
            CP16(sb + PXW + (uint32_t)(wid * 512 + row * 64 + ch * 16),
                 (const char*)(g_xw + ((size_t)(n0 + row) * TT + t) * FOURH + jb * 32) + ch * 16);
        }
        #pragma unroll
        for (int cc = 0; cc < 16; cc++) {
            const int c = (cc + rot) & 15;
            const int k0 = c * 64;
            const uint32_t bb = sb + PB + (uint32_t)(cc * 8192);
            CP16(bb + bo0, (const char*)(Bg + (size_t)(n0 + bl_row0) * DD + k0) + bl_ch0 * 16);
            CP16(bb + bo1, (const char*)(Bg + (size_t)(n0 + bl_row1) * DD + k0) + bl_ch1 * 16);
            CP_COMMIT();
        }

        // 4 independent accumulator chains: [mt][k16-parity]
        float accE[2][4], accO[2][4];
        #pragma unroll
        for (int mt = 0; mt < 2; mt++)
            #pragma unroll
            for (int q = 0; q < 4; q++) { accE[mt][q] = 0.0f; accO[mt][q] = 0.0f; }

        // ---- pure-issue mainloop; wait counts descend 15..0 ----
        #define STEP_CHUNK(CC)                                                          \
        {                                                                               \
            CP_WAIT(15 - (CC));                                                         \
            __syncwarp();                                                               \
            const int c = ((CC) + rot) & 15;                                            \
            const uint32_t bst = sb + PB + (uint32_t)((CC) * 8192);                     \
            const uint32_t ahc = sb + PA + (uint32_t)(c * 4096);                        \
            _Pragma("unroll")                                                           \
            for (int k2 = 0; k2 < 2; k2++) {                                            \
                uint32_t bh[4];                                                         \
                const uint32_t bo = (uint32_t)((n0 + b_row) * 128)                      \
                                  + (uint32_t)((k2 * 64 + b_mat * 16) ^ (b_row * 16));  \
                LDSM4(bh[0], bh[1], bh[2], bh[3], bst + bo);                            \
                uint32_t a0[2][4], a1[2][4];                                            \
                _Pragma("unroll")                                                       \
                for (int mt = 0; mt < 2; mt++) {                                        \
                    const uint32_t ka0 = ((uint32_t)(k2 * 64) + a_k) ^ a_x;             \
                    const uint32_t ka1 = ((uint32_t)(k2 * 64 + 32) + a_k) ^ a_x;        \
                    const uint32_t ar = (uint32_t)((mt * 16 + a_r) * 128);              \
                    LDSM4(a0[mt][0], a0[mt][1], a0[mt][2], a0[mt][3], ahc + ar + ka0);  \
                    LDSM4(a1[mt][0], a1[mt][1], a1[mt][2], a1[mt][3], ahc + ar + ka1);  \
                }                                                                       \
                _Pragma("unroll")                                                       \
                for (int mt = 0; mt < 2; mt++)                                          \
                    MMA_F16(accE[mt][0], accE[mt][1], accE[mt][2], accE[mt][3],         \
                            a0[mt][0], a0[mt][1], a0[mt][2], a0[mt][3], bh[0], bh[1]);  \
                _Pragma("unroll")                                                       \
                for (int mt = 0; mt < 2; mt++)                                          \
                    MMA_F16(accO[mt][0], accO[mt][1], accO[mt][2], accO[mt][3],         \
                            a1[mt][0], a1[mt][1], a1[mt][2], a1[mt][3], bh[2], bh[3]);  \
            }                                                                           \
        }
        STEP_CHUNK(0)  STEP_CHUNK(1)  STEP_CHUNK(2)  STEP_CHUNK(3)
        STEP_CHUNK(4)  STEP_CHUNK(5)  STEP_CHUNK(6)  STEP_CHUNK(7)
        STEP_CHUNK(8)  STEP_CHUNK(9)  STEP_CHUNK(10) STEP_CHUNK(11)
        STEP_CHUNK(12) STEP_CHUNK(13) STEP_CHUNK(14) STEP_CHUNK(15)
        #undef STEP_CHUNK

        // merge chains, stage acc -> asw[n_local][j'] (stride 36), gates
        float* asw = (float*)(smem + PASW + wid * 1152);
        #pragma unroll
        for (int mt = 0; mt < 2; mt++) {
            asw[(tig * 2 + 0) * 36 + mt * 16 + gid]     = accE[mt][0] + accO[mt][0];
            asw[(tig * 2 + 1) * 36 + mt * 16 + gid]     = accE[mt][1] + accO[mt][1];
            asw[(tig * 2 + 0) * 36 + mt * 16 + gid + 8] = accE[mt][2] + accO[mt][2];
            asw[(tig * 2 + 1) * 36 + mt * 16 + gid + 8] = accE[mt][3] + accO[mt][3];
        }
        __syncwarp();

        {
            const __half* xws = (const __half*)(smem + PXW) + wid * 256;
            __half* nh = g_h[(t + 1) & 1];
            #pragma unroll
            for (int i = 0; i < 2; i++) {
                const int p = lane + i * 32;    // 0..63
                const int nl = p >> 3;          // 0..7
                const int jhl = p & 7;          // 0..7
                const float* ar = asw + nl * 36 + jhl * 4;
                const __half2* xr = (const __half2*)(xws + nl * 32 + jhl * 4);
                float2 x01 = __half22float2(xr[0]);
                float2 x23 = __half22float2(xr[1]);
                float ig = fsigmoid(ar[0] + x01.x);
                float fg = fsigmoid(ar[1] + x01.y);
                float og = fsigmoid(ar[2] + x23.x);
                float gg = ftanh(ar[3] + x23.y);
                float cn = fg * creg[i] + ig * gg;
                creg[i] = cn;
                float h = og * ftanh(cn);
                const int n = n0 + nl;
                const int jg = jb * 8 + jhl;
                out[((size_t)n * TT + t) * HH + jg] = h;
                nh[n * HH + jg] = __float2half_rn(h);
            }
        }

        // cheap global barrier: release-add publish, acquire poll (tid 0 only)
        __syncthreads();
        if (tid == 0) {
            red_rel_add(&g_bar, 1u);
            const unsigned target = (t + 1u) * (unsigned)P_CTAS;
            while (ld_acq(&g_bar) < target) { }
        }
        __syncthreads();
    }
}

// ---------------------------------------------------------------------------
extern "C" void kernel_launch(void* const* d_in, const int* in_sizes, int n_in,
                              void* d_out, int out_size)
{
    const float* x  = (const float*)d_in[0];   // (64, 512, 1024)
    const float* h0 = (const float*)d_in[1];   // (64, 1024)
    const float* Wx = (const float*)d_in[2];   // (1024, 4096)
    const float* Wh = (const float*)d_in[3];   // (1024, 4096)
    const float* b  = (const float*)d_in[4];   // (4096,)
    float* out = (float*)d_out;                // (64, 512, 1024)

    cudaFuncSetAttribute(xw_gemm_mma,     cudaFuncAttributeMaxDynamicSharedMemorySize, G_SMEM);
    cudaFuncSetAttribute(lstm_persistent, cudaFuncAttributeMaxDynamicSharedMemorySize, P_SMEM);

    __half *wxt, *wht;
    cudaGetSymbolAddress((void**)&wxt, g_wxt);
    cudaGetSymbolAddress((void**)&wht, g_wht);

    prep_small_kernel<<<64, 1024>>>(h0, b);
    split_x_kernel<<<(NB * TT * DD / 4) / 256, 256>>>(x);
    transpose_perm_kernel<<<dim3(DD / 32, FOURH / 32), dim3(32, 8)>>>(Wx, wxt);
    transpose_perm_kernel<<<dim3(DD / 32, FOURH / 32), dim3(32, 8)>>>(Wh, wht);

    xw_gemm_mma<<<dim3(32, 256), 256, G_SMEM>>>();

    lstm_persistent<<<P_CTAS, 256, P_SMEM>>>(out);
}